// round 9
// baseline (speedup 1.0000x reference)
#include <cuda_runtime.h>
#include <cuda_bf16.h>
#include <cstdint>
#include <math.h>

#define BATCH 2
#define SEQ   2048
#define CDIM  2048
#define NHEAD 16
#define NKV   4
#define HD    128
#define NREP  4
#define WIN   512
#define FDIM  3072
#define MTOT  (BATCH*SEQ)   // 4096
#define ATT_SCALE 0.08838834764831845f

// ---------------- scratch (__device__ globals; no allocations) -------------
__device__ float g_qkv[(size_t)MTOT * FDIM];           // 50.3 MB
__device__ __nv_bfloat16 g_xh[(size_t)MTOT * CDIM];
__device__ __nv_bfloat16 g_xl[(size_t)MTOT * CDIM];
__device__ __nv_bfloat16 g_wqh[(size_t)FDIM * CDIM];
__device__ __nv_bfloat16 g_wql[(size_t)FDIM * CDIM];
__device__ __nv_bfloat16 g_wph[(size_t)CDIM * CDIM];
__device__ __nv_bfloat16 g_wpl[(size_t)CDIM * CDIM];
__device__ __nv_bfloat16 g_yh[(size_t)MTOT * CDIM];
__device__ __nv_bfloat16 g_yl[(size_t)MTOT * CDIM];

// ---------------- helpers --------------------------------------------------
__device__ __forceinline__ uint32_t smem_to_u32(const void* p) {
    uint32_t a;
    asm("{ .reg .u64 t; cvta.to.shared.u64 t, %1; cvt.u32.u64 %0, t; }" : "=r"(a) : "l"(p));
    return a;
}
__device__ __forceinline__ void cp_async16(uint32_t dst, const void* src) {
    asm volatile("cp.async.cg.shared.global [%0], [%1], 16;" :: "r"(dst), "l"(src));
}
__device__ __forceinline__ void cp_commit() {
    asm volatile("cp.async.commit_group;");
}
template <int N>
__device__ __forceinline__ void cp_wait() {
    asm volatile("cp.async.wait_group %0;" :: "n"(N));
}
__device__ __forceinline__ void ldmatrix_x4(uint32_t* r, uint32_t addr) {
    asm volatile("ldmatrix.sync.aligned.m8n8.x4.shared.b16 {%0,%1,%2,%3}, [%4];"
        : "=r"(r[0]), "=r"(r[1]), "=r"(r[2]), "=r"(r[3]) : "r"(addr));
}
__device__ __forceinline__ void ldmatrix_x4_trans(uint32_t* r, uint32_t addr) {
    asm volatile("ldmatrix.sync.aligned.m8n8.x4.trans.shared.b16 {%0,%1,%2,%3}, [%4];"
        : "=r"(r[0]), "=r"(r[1]), "=r"(r[2]), "=r"(r[3]) : "r"(addr));
}
__device__ __forceinline__ void mma_bf16(float* c, const uint32_t* a, const uint32_t* b) {
    asm volatile(
        "mma.sync.aligned.m16n8k16.row.col.f32.bf16.bf16.f32 "
        "{%0,%1,%2,%3}, {%4,%5,%6,%7}, {%8,%9}, {%0,%1,%2,%3};"
        : "+f"(c[0]), "+f"(c[1]), "+f"(c[2]), "+f"(c[3])
        : "r"(a[0]), "r"(a[1]), "r"(a[2]), "r"(a[3]), "r"(b[0]), "r"(b[1]));
}
__device__ __forceinline__ uint32_t pack_bf16x2(float lo, float hi) {
    __nv_bfloat162 t = __floats2bfloat162_rn(lo, hi);
    return *(uint32_t*)&t;
}

// ---------------- split fp32 -> bf16 hi + bf16 lo --------------------------
__global__ void split_kernel(const float* __restrict__ src,
                             __nv_bfloat16* __restrict__ hi,
                             __nv_bfloat16* __restrict__ lo, int n)
{
    int i = blockIdx.x * blockDim.x + threadIdx.x;
    if (i >= n) return;
    float v = src[i];
    __nv_bfloat16 h = __float2bfloat16(v);
    hi[i] = h;
    lo[i] = __float2bfloat16(v - __bfloat162float(h));
}

// ---------------- bf16x3 NT GEMM via mma.sync, 4-stage cp.async ------------
#define GPAD     40
#define GROW_B   (GPAD * 2)
#define GMAT_B   (128 * GROW_B)
#define GSTG_B   (4 * GMAT_B)          // 40960 per stage
#define GNSTAGE  4
#define GEMM_SMEM (GNSTAGE * GSTG_B)   // 163840

__global__ void __launch_bounds__(256)
gemm_bf16x3_kernel(const __nv_bfloat16* __restrict__ Ah, const __nv_bfloat16* __restrict__ Al,
                   const __nv_bfloat16* __restrict__ Bh, const __nv_bfloat16* __restrict__ Bl,
                   float* __restrict__ C, int M, int N, int K)
{
    extern __shared__ __align__(128) char smem[];
    const uint32_t sbase = smem_to_u32(smem);

    const int tid  = threadIdx.x;
    const int wid  = tid >> 5;
    const int lane = tid & 31;
    const int warp_m = wid & 1;
    const int warp_n = wid >> 1;
    const int m0 = blockIdx.y * 128;
    const int n0 = blockIdx.x * 128;

    float acc[4][4][4];
    #pragma unroll
    for (int i = 0; i < 4; ++i)
        #pragma unroll
        for (int j = 0; j < 4; ++j)
            #pragma unroll
            for (int r = 0; r < 4; ++r) acc[i][j][r] = 0.f;

    const int NIT = K >> 5;

    auto issue_stage = [&](int it) {
        const int s = it & (GNSTAGE - 1);
        const int k0 = it * 32;
        const char* gA[4] = {
            (const char*)(Ah + (size_t)m0 * K + k0), (const char*)(Al + (size_t)m0 * K + k0),
            (const char*)(Bh + (size_t)n0 * K + k0), (const char*)(Bl + (size_t)n0 * K + k0)};
        const size_t grs = (size_t)K * 2;
        #pragma unroll
        for (int t = 0; t < 4; ++t) {
            #pragma unroll
            for (int i = 0; i < 2; ++i) {
                int chunk = tid + i * 256;
                int r = chunk >> 2, c = (chunk & 3) * 16;
                uint32_t dst = sbase + s * GSTG_B + t * GMAT_B + r * GROW_B + c;
                cp_async16(dst, gA[t] + (size_t)r * grs + c);
            }
        }
        cp_commit();
    };

    // prologue: 3 stages in flight
    issue_stage(0);
    issue_stage(1);
    issue_stage(2);

    for (int it = 0; it < NIT; ++it) {
        cp_wait<2>();          // stage `it` resident (groups always advance below)
        __syncthreads();       // slot (it-1) reads done by ALL warps; data visible

        if (it + 3 < NIT) issue_stage(it + 3);   // writes slot (it-1)&3 — safe
        else              cp_commit();            // keep group count advancing

        const int s = it & (GNSTAGE - 1);
        const uint32_t sA_h = sbase + s * GSTG_B + 0 * GMAT_B;
        const uint32_t sA_l = sbase + s * GSTG_B + 1 * GMAT_B;
        const uint32_t sB_h = sbase + s * GSTG_B + 2 * GMAT_B;
        const uint32_t sB_l = sbase + s * GSTG_B + 3 * GMAT_B;

        const int lg = lane >> 3;
        #pragma unroll
        for (int ks = 0; ks < 2; ++ks) {
            const int kc = ks * 16;
            uint32_t ah[4][4], al[4][4];
            #pragma unroll
            for (int mt = 0; mt < 4; ++mt) {
                uint32_t off = (uint32_t)((warp_m * 64 + mt * 16 + (lane & 7) + (lg & 1) * 8) * GROW_B
                                          + (kc + (lg >> 1) * 8) * 2);
                ldmatrix_x4(ah[mt], sA_h + off);
                ldmatrix_x4(al[mt], sA_l + off);
            }
            uint32_t bh[2][4], bl[2][4];
            #pragma unroll
            for (int p = 0; p < 2; ++p) {
                uint32_t off = (uint32_t)((warp_n * 32 + p * 16 + (lane & 7) + (lg >> 1) * 8) * GROW_B
                                          + (kc + (lg & 1) * 8) * 2);
                ldmatrix_x4(bh[p], sB_h + off);
                ldmatrix_x4(bl[p], sB_l + off);
            }
            #pragma unroll
            for (int mt = 0; mt < 4; ++mt)
                #pragma unroll
                for (int nt = 0; nt < 4; ++nt) {
                    const uint32_t* bhp = &bh[nt >> 1][(nt & 1) * 2];
                    const uint32_t* blp = &bl[nt >> 1][(nt & 1) * 2];
                    mma_bf16(acc[mt][nt], ah[mt], bhp);
                    mma_bf16(acc[mt][nt], ah[mt], blp);
                    mma_bf16(acc[mt][nt], al[mt], bhp);
                }
        }
    }

    #pragma unroll
    for (int mt = 0; mt < 4; ++mt) {
        #pragma unroll
        for (int nt = 0; nt < 4; ++nt) {
            int m = m0 + warp_m * 64 + mt * 16 + (lane >> 2);
            int n = n0 + warp_n * 32 + nt * 8 + (lane & 3) * 2;
            *(float2*)&C[(size_t)m * N + n]       = make_float2(acc[mt][nt][0], acc[mt][nt][1]);
            *(float2*)&C[(size_t)(m + 8) * N + n] = make_float2(acc[mt][nt][2], acc[mt][nt][3]);
        }
    }
}

// ---------------- RoPE -----------------------------------------------------
__global__ void rope_kernel(const float* __restrict__ fcos,
                            const float* __restrict__ fsin)
{
    const int PAIRS_PER_TOK = (NHEAD + NKV) * (HD / 2);
    int idx = blockIdx.x * blockDim.x + threadIdx.x;
    if (idx >= MTOT * PAIRS_PER_TOK) return;
    int tok = idx / PAIRS_PER_TOK;
    int r = idx % PAIRS_PER_TOK;
    int t = tok % SEQ;
    int h = r / (HD / 2);
    int p = r % (HD / 2);
    float c = __ldg(&fcos[t * (HD / 2) + p]);
    float s = __ldg(&fsin[t * (HD / 2) + p]);
    float* base = &g_qkv[(size_t)tok * FDIM + h * HD + 2 * p];
    float xr = base[0], xi = base[1];
    base[0] = xr * c - xi * s;
    base[1] = xr * s + xi * c;
}

// ---------------- windowed flash attention via mma.sync bf16x3 -------------
#define AROW    136
#define AROW_B  (AROW * 2)
#define ABUF_B  (128 * AROW_B)
#define ATT_SMEM (6 * ABUF_B)

__global__ void __launch_bounds__(256) attn_mma_kernel()
{
    extern __shared__ __align__(128) char asmem[];
    const uint32_t sb  = smem_to_u32(asmem);
    const uint32_t sQh = sb,              sQl = sb + ABUF_B;
    const uint32_t sKh = sb + 2*ABUF_B,   sKl = sb + 3*ABUF_B;
    const uint32_t sVh = sb + 4*ABUF_B,   sVl = sb + 5*ABUF_B;
    __nv_bfloat16* Qh = (__nv_bfloat16*)asmem;
    __nv_bfloat16* Ql = Qh + 128*AROW;
    __nv_bfloat16* Kh = Qh + 2*128*AROW;
    __nv_bfloat16* Kl = Qh + 3*128*AROW;
    __nv_bfloat16* Vh = Qh + 4*128*AROW;
    __nv_bfloat16* Vl = Qh + 5*128*AROW;

    const int tid  = threadIdx.x;
    const int w    = tid >> 5;
    const int lane = tid & 31;
    const int lg   = lane >> 3;
    const int bh   = blockIdx.y;
    const int b    = bh / NHEAD;
    const int h    = bh % NHEAD;
    const int kvh  = h / NREP;
    const int q0   = blockIdx.x * 128;

    #pragma unroll
    for (int i = 0; i < 16; ++i) {
        int v = tid + i * 256;
        int m = v >> 5, dq = (v & 31) * 4;
        float4 q = *(const float4*)&g_qkv[(size_t)(b * SEQ + q0 + m) * FDIM + h * HD + dq];
        float f[4] = {q.x, q.y, q.z, q.w};
        #pragma unroll
        for (int e = 0; e < 4; e += 2) {
            __nv_bfloat16 h0 = __float2bfloat16(f[e]);
            __nv_bfloat16 h1 = __float2bfloat16(f[e+1]);
            float l0 = f[e]   - __bfloat162float(h0);
            float l1 = f[e+1] - __bfloat162float(h1);
            *(uint32_t*)&Qh[m * AROW + dq + e] = pack_bf16x2(__bfloat162float(h0), __bfloat162float(h1));
            *(uint32_t*)&Ql[m * AROW + dq + e] = pack_bf16x2(l0, l1);
        }
    }

    float m_i[2] = {-1e30f, -1e30f};
    float l_i[2] = {0.f, 0.f};
    float oacc[16][4];
    #pragma unroll
    for (int i = 0; i < 16; ++i)
        #pragma unroll
        for (int r = 0; r < 4; ++r) oacc[i][r] = 0.f;

    const int row_r = q0 + w * 16 + (lane >> 2);
    const int kt_lo = (q0 >= WIN) ? (q0 - WIN) : 0;

    for (int kt = kt_lo; kt <= q0; kt += 128) {
        __syncthreads();
        #pragma unroll
        for (int i = 0; i < 16; ++i) {
            int v = tid + i * 256;
            int c = v >> 5, dq = (v & 31) * 4;
            const size_t tokbase = (size_t)(b * SEQ + kt + c) * FDIM;
            float4 kk = *(const float4*)&g_qkv[tokbase + NHEAD * HD + kvh * HD + dq];
            float kf[4] = {kk.x, kk.y, kk.z, kk.w};
            #pragma unroll
            for (int e = 0; e < 4; e += 2) {
                __nv_bfloat16 h0 = __float2bfloat16(kf[e]);
                __nv_bfloat16 h1 = __float2bfloat16(kf[e+1]);
                *(uint32_t*)&Kh[c * AROW + dq + e] =
                    pack_bf16x2(__bfloat162float(h0), __bfloat162float(h1));
                *(uint32_t*)&Kl[c * AROW + dq + e] =
                    pack_bf16x2(kf[e] - __bfloat162float(h0), kf[e+1] - __bfloat162float(h1));
            }
            float4 vv = *(const float4*)&g_qkv[tokbase + (NHEAD + NKV) * HD + kvh * HD + dq];
            float vf[4] = {vv.x, vv.y, vv.z, vv.w};
            #pragma unroll
            for (int e = 0; e < 4; e += 2) {
                __nv_bfloat16 h0 = __float2bfloat16(vf[e]);
                __nv_bfloat16 h1 = __float2bfloat16(vf[e+1]);
                *(uint32_t*)&Vh[c * AROW + dq + e] =
                    pack_bf16x2(__bfloat162float(h0), __bfloat162float(h1));
                *(uint32_t*)&Vl[c * AROW + dq + e] =
                    pack_bf16x2(vf[e] - __bfloat162float(h0), vf[e+1] - __bfloat162float(h1));
            }
        }
        __syncthreads();

        float sacc[16][4];
        #pragma unroll
        for (int i = 0; i < 16; ++i)
            #pragma unroll
            for (int r = 0; r < 4; ++r) sacc[i][r] = 0.f;

        #pragma unroll
        for (int ks = 0; ks < 8; ++ks) {
            uint32_t aQh[4], aQl[4];
            uint32_t aoff = (uint32_t)((w * 16 + (lane & 7) + (lg & 1) * 8) * AROW_B
                                       + (ks * 16 + (lg >> 1) * 8) * 2);
            ldmatrix_x4(aQh, sQh + aoff);
            ldmatrix_x4(aQl, sQl + aoff);
            #pragma unroll
            for (int p16 = 0; p16 < 8; ++p16) {
                uint32_t bK[4], bKl[4];
                uint32_t boff = (uint32_t)((p16 * 16 + (lane & 7) + (lg >> 1) * 8) * AROW_B
                                           + (ks * 16 + (lg & 1) * 8) * 2);
                ldmatrix_x4(bK,  sKh + boff);
                ldmatrix_x4(bKl, sKl + boff);
                mma_bf16(sacc[2*p16],   aQh, &bK[0]);
                mma_bf16(sacc[2*p16],   aQh, &bKl[0]);
                mma_bf16(sacc[2*p16],   aQl, &bK[0]);
                mma_bf16(sacc[2*p16+1], aQh, &bK[2]);
                mma_bf16(sacc[2*p16+1], aQh, &bKl[2]);
                mma_bf16(sacc[2*p16+1], aQl, &bK[2]);
            }
        }

        #pragma unroll
        for (int nf = 0; nf < 16; ++nf) {
            int col = kt + nf * 8 + (lane & 3) * 2;
            #pragma unroll
            for (int e = 0; e < 2; ++e) {
                int cj = col + e;
                bool k0 = (cj <= row_r)     && (cj >= row_r - (WIN - 1));
                bool k1 = (cj <= row_r + 8) && (cj >= row_r + 8 - (WIN - 1));
                sacc[nf][e]     = k0 ? sacc[nf][e]     * ATT_SCALE : -1e30f;
                sacc[nf][e + 2] = k1 ? sacc[nf][e + 2] * ATT_SCALE : -1e30f;
            }
        }

        float mx0 = -1e30f, mx1 = -1e30f;
        #pragma unroll
        for (int nf = 0; nf < 16; ++nf) {
            mx0 = fmaxf(mx0, fmaxf(sacc[nf][0], sacc[nf][1]));
            mx1 = fmaxf(mx1, fmaxf(sacc[nf][2], sacc[nf][3]));
        }
        #pragma unroll
        for (int o = 1; o < 4; o <<= 1) {
            mx0 = fmaxf(mx0, __shfl_xor_sync(0xffffffffu, mx0, o));
            mx1 = fmaxf(mx1, __shfl_xor_sync(0xffffffffu, mx1, o));
        }
        float mn0 = fmaxf(m_i[0], mx0), mn1 = fmaxf(m_i[1], mx1);
        float al0 = __expf(m_i[0] - mn0), al1 = __expf(m_i[1] - mn1);
        float rs0 = 0.f, rs1 = 0.f;
        #pragma unroll
        for (int nf = 0; nf < 16; ++nf) {
            sacc[nf][0] = __expf(sacc[nf][0] - mn0);
            sacc[nf][1] = __expf(sacc[nf][1] - mn0);
            sacc[nf][2] = __expf(sacc[nf][2] - mn1);
            sacc[nf][3] = __expf(sacc[nf][3] - mn1);
            rs0 += sacc[nf][0] + sacc[nf][1];
            rs1 += sacc[nf][2] + sacc[nf][3];
        }
        #pragma unroll
        for (int o = 1; o < 4; o <<= 1) {
            rs0 += __shfl_xor_sync(0xffffffffu, rs0, o);
            rs1 += __shfl_xor_sync(0xffffffffu, rs1, o);
        }
        l_i[0] = l_i[0] * al0 + rs0;  m_i[0] = mn0;
        l_i[1] = l_i[1] * al1 + rs1;  m_i[1] = mn1;
        #pragma unroll
        for (int nf = 0; nf < 16; ++nf) {
            oacc[nf][0] *= al0; oacc[nf][1] *= al0;
            oacc[nf][2] *= al1; oacc[nf][3] *= al1;
        }

        #pragma unroll
        for (int kc = 0; kc < 8; ++kc) {
            uint32_t aph[4], apl[4];
            #pragma unroll
            for (int half = 0; half < 2; ++half) {
                const float* sf = sacc[2 * kc + half];
                __nv_bfloat16 h0 = __float2bfloat16(sf[0]);
                __nv_bfloat16 h1 = __float2bfloat16(sf[1]);
                __nv_bfloat16 h2 = __float2bfloat16(sf[2]);
                __nv_bfloat16 h3 = __float2bfloat16(sf[3]);
                aph[half * 2 + 0] = pack_bf16x2(__bfloat162float(h0), __bfloat162float(h1));
                aph[half * 2 + 1] = pack_bf16x2(__bfloat162float(h2), __bfloat162float(h3));
                apl[half * 2 + 0] = pack_bf16x2(sf[0] - __bfloat162float(h0),
                                                sf[1] - __bfloat162float(h1));
                apl[half * 2 + 1] = pack_bf16x2(sf[2] - __bfloat162float(h2),
                                                sf[3] - __bfloat162float(h3));
            }
            #pragma unroll
            for (int p16 = 0; p16 < 8; ++p16) {
                uint32_t bV[4], bVl[4];
                uint32_t boff = (uint32_t)((kc * 16 + (lane & 7) + (lg & 1) * 8) * AROW_B
                                           + (p16 * 16 + (lg >> 1) * 8) * 2);
                ldmatrix_x4_trans(bV,  sVh + boff);
                ldmatrix_x4_trans(bVl, sVl + boff);
                mma_bf16(oacc[2*p16],   aph, &bV[0]);
                mma_bf16(oacc[2*p16],   aph, &bVl[0]);
                mma_bf16(oacc[2*p16],   apl, &bV[0]);
                mma_bf16(oacc[2*p16+1], aph, &bV[2]);
                mma_bf16(oacc[2*p16+1], aph, &bVl[2]);
                mma_bf16(oacc[2*p16+1], apl, &bV[2]);
            }
        }
    }

    float inv0 = 1.f / l_i[0];
    float inv1 = 1.f / l_i[1];
    #pragma unroll
    for (int nf = 0; nf < 16; ++nf) {
        int d0 = nf * 8 + (lane & 3) * 2;
        size_t base0 = (size_t)(b * SEQ + row_r)     * CDIM + h * HD + d0;
        size_t base1 = (size_t)(b * SEQ + row_r + 8) * CDIM + h * HD + d0;
        float v00 = oacc[nf][0] * inv0, v01 = oacc[nf][1] * inv0;
        float v10 = oacc[nf][2] * inv1, v11 = oacc[nf][3] * inv1;
        __nv_bfloat16 h00 = __float2bfloat16(v00), h01 = __float2bfloat16(v01);
        __nv_bfloat16 h10 = __float2bfloat16(v10), h11 = __float2bfloat16(v11);
        *(uint32_t*)&g_yh[base0] = pack_bf16x2(__bfloat162float(h00), __bfloat162float(h01));
        *(uint32_t*)&g_yl[base0] = pack_bf16x2(v00 - __bfloat162float(h00),
                                               v01 - __bfloat162float(h01));
        *(uint32_t*)&g_yh[base1] = pack_bf16x2(__bfloat162float(h10), __bfloat162float(h11));
        *(uint32_t*)&g_yl[base1] = pack_bf16x2(v10 - __bfloat162float(h10),
                                               v11 - __bfloat162float(h11));
    }
}

// ---------------------------------------------------------------------------
extern "C" void kernel_launch(void* const* d_in, const int* in_sizes, int n_in,
                              void* d_out, int out_size)
{
    (void)in_sizes; (void)n_in; (void)out_size;
    const float* x      = (const float*)d_in[0];
    const float* w_qkv  = (const float*)d_in[1];
    const float* w_proj = (const float*)d_in[2];
    const float* fcos   = (const float*)d_in[3];
    const float* fsin   = (const float*)d_in[4];
    float* out = (float*)d_out;

    void *p_qkv, *p_xh, *p_xl, *p_wqh, *p_wql, *p_wph, *p_wpl, *p_yh, *p_yl;
    cudaGetSymbolAddress(&p_qkv, g_qkv);
    cudaGetSymbolAddress(&p_xh,  g_xh);
    cudaGetSymbolAddress(&p_xl,  g_xl);
    cudaGetSymbolAddress(&p_wqh, g_wqh);
    cudaGetSymbolAddress(&p_wql, g_wql);
    cudaGetSymbolAddress(&p_wph, g_wph);
    cudaGetSymbolAddress(&p_wpl, g_wpl);
    cudaGetSymbolAddress(&p_yh,  g_yh);
    cudaGetSymbolAddress(&p_yl,  g_yl);

    cudaFuncSetAttribute(gemm_bf16x3_kernel,
                         cudaFuncAttributeMaxDynamicSharedMemorySize, GEMM_SMEM);
    cudaFuncSetAttribute(attn_mma_kernel,
                         cudaFuncAttributeMaxDynamicSharedMemorySize, ATT_SMEM);

    // splits
    {
        int n = MTOT * CDIM;
        split_kernel<<<(n + 255) / 256, 256>>>(x, (__nv_bfloat16*)p_xh, (__nv_bfloat16*)p_xl, n);
        n = FDIM * CDIM;
        split_kernel<<<(n + 255) / 256, 256>>>(w_qkv, (__nv_bfloat16*)p_wqh, (__nv_bfloat16*)p_wql, n);
        n = CDIM * CDIM;
        split_kernel<<<(n + 255) / 256, 256>>>(w_proj, (__nv_bfloat16*)p_wph, (__nv_bfloat16*)p_wpl, n);
    }
    // QKV projection
    {
        dim3 grid(FDIM / 128, MTOT / 128);
        gemm_bf16x3_kernel<<<grid, 256, GEMM_SMEM>>>(
            (const __nv_bfloat16*)p_xh, (const __nv_bfloat16*)p_xl,
            (const __nv_bfloat16*)p_wqh, (const __nv_bfloat16*)p_wql,
            (float*)p_qkv, MTOT, FDIM, CDIM);
    }
    // RoPE
    {
        int total = MTOT * (NHEAD + NKV) * (HD / 2);
        rope_kernel<<<(total + 255) / 256, 256>>>(fcos, fsin);
    }
    // Attention
    {
        dim3 grid(SEQ / 128, BATCH * NHEAD);
        attn_mma_kernel<<<grid, 256, ATT_SMEM>>>();
    }
    // Output projection
    {
        dim3 grid(CDIM / 128, MTOT / 128);
        gemm_bf16x3_kernel<<<grid, 256, GEMM_SMEM>>>(
            (const __nv_bfloat16*)p_yh, (const __nv_bfloat16*)p_yl,
            (const __nv_bfloat16*)p_wph, (const __nv_bfloat16*)p_wpl,
            out, MTOT, CDIM, CDIM);
    }
}

// round 10
// speedup vs baseline: 1.1220x; 1.1220x over previous
#include <cuda_runtime.h>
#include <cuda_bf16.h>
#include <cstdint>
#include <math.h>

#define BATCH 2
#define SEQ   2048
#define CDIM  2048
#define NHEAD 16
#define NKV   4
#define HD    128
#define NREP  4
#define WIN   512
#define FDIM  3072
#define MTOT  (BATCH*SEQ)   // 4096
#define ATT_SCALE 0.08838834764831845f

// ---------------- scratch (__device__ globals; no allocations) -------------
__device__ float g_qkv[(size_t)MTOT * FDIM];
__device__ __nv_bfloat16 g_xh[(size_t)MTOT * CDIM];
__device__ __nv_bfloat16 g_xl[(size_t)MTOT * CDIM];
__device__ __nv_bfloat16 g_wqh[(size_t)FDIM * CDIM];
__device__ __nv_bfloat16 g_wql[(size_t)FDIM * CDIM];
__device__ __nv_bfloat16 g_wph[(size_t)CDIM * CDIM];
__device__ __nv_bfloat16 g_wpl[(size_t)CDIM * CDIM];
__device__ __nv_bfloat16 g_yh[(size_t)MTOT * CDIM];
__device__ __nv_bfloat16 g_yl[(size_t)MTOT * CDIM];

// ---------------- helpers --------------------------------------------------
__device__ __forceinline__ uint32_t smem_to_u32(const void* p) {
    uint32_t a;
    asm("{ .reg .u64 t; cvta.to.shared.u64 t, %1; cvt.u32.u64 %0, t; }" : "=r"(a) : "l"(p));
    return a;
}
__device__ __forceinline__ void cp_async16(uint32_t dst, const void* src) {
    asm volatile("cp.async.cg.shared.global [%0], [%1], 16;" :: "r"(dst), "l"(src));
}
__device__ __forceinline__ void cp_commit() {
    asm volatile("cp.async.commit_group;");
}
template <int N>
__device__ __forceinline__ void cp_wait() {
    asm volatile("cp.async.wait_group %0;" :: "n"(N));
}
__device__ __forceinline__ void ldmatrix_x4(uint32_t* r, uint32_t addr) {
    asm volatile("ldmatrix.sync.aligned.m8n8.x4.shared.b16 {%0,%1,%2,%3}, [%4];"
        : "=r"(r[0]), "=r"(r[1]), "=r"(r[2]), "=r"(r[3]) : "r"(addr));
}
__device__ __forceinline__ void ldmatrix_x4_trans(uint32_t* r, uint32_t addr) {
    asm volatile("ldmatrix.sync.aligned.m8n8.x4.trans.shared.b16 {%0,%1,%2,%3}, [%4];"
        : "=r"(r[0]), "=r"(r[1]), "=r"(r[2]), "=r"(r[3]) : "r"(addr));
}
__device__ __forceinline__ void mma_bf16(float* c, const uint32_t* a, const uint32_t* b) {
    asm volatile(
        "mma.sync.aligned.m16n8k16.row.col.f32.bf16.bf16.f32 "
        "{%0,%1,%2,%3}, {%4,%5,%6,%7}, {%8,%9}, {%0,%1,%2,%3};"
        : "+f"(c[0]), "+f"(c[1]), "+f"(c[2]), "+f"(c[3])
        : "r"(a[0]), "r"(a[1]), "r"(a[2]), "r"(a[3]), "r"(b[0]), "r"(b[1]));
}
__device__ __forceinline__ uint32_t pack_bf16x2(float lo, float hi) {
    __nv_bfloat162 t = __floats2bfloat162_rn(lo, hi);
    return *(uint32_t*)&t;
}

// ---------------- split fp32 -> bf16 hi + bf16 lo --------------------------
__global__ void split_kernel(const float* __restrict__ src,
                             __nv_bfloat16* __restrict__ hi,
                             __nv_bfloat16* __restrict__ lo, int n)
{
    int i = blockIdx.x * blockDim.x + threadIdx.x;
    if (i >= n) return;
    float v = src[i];
    __nv_bfloat16 h = __float2bfloat16(v);
    hi[i] = h;
    lo[i] = __float2bfloat16(v - __bfloat162float(h));
}

// ---------------- bf16x3 NT GEMM: R8 2-stage pipeline + term-major mma -----
#define GPAD     40
#define GROW_B   (GPAD * 2)
#define GMAT_B   (128 * GROW_B)
#define GSTG_B   (4 * GMAT_B)
#define GEMM_SMEM (2 * GSTG_B)         // 81920 -> 2 CTAs/SM

__global__ void __launch_bounds__(256)
gemm_bf16x3_kernel(const __nv_bfloat16* __restrict__ Ah, const __nv_bfloat16* __restrict__ Al,
                   const __nv_bfloat16* __restrict__ Bh, const __nv_bfloat16* __restrict__ Bl,
                   float* __restrict__ C, int M, int N, int K)
{
    extern __shared__ __align__(128) char smem[];
    const uint32_t sbase = smem_to_u32(smem);

    const int tid  = threadIdx.x;
    const int wid  = tid >> 5;
    const int lane = tid & 31;
    const int warp_m = wid & 1;
    const int warp_n = wid >> 1;
    const int m0 = blockIdx.y * 128;
    const int n0 = blockIdx.x * 128;

    float acc[4][4][4];
    #pragma unroll
    for (int i = 0; i < 4; ++i)
        #pragma unroll
        for (int j = 0; j < 4; ++j)
            #pragma unroll
            for (int r = 0; r < 4; ++r) acc[i][j][r] = 0.f;

    const int NIT = K >> 5;

    auto issue_stage = [&](int it) {
        const int s = it & 1;
        const int k0 = it * 32;
        const char* gA[4] = {
            (const char*)(Ah + (size_t)m0 * K + k0), (const char*)(Al + (size_t)m0 * K + k0),
            (const char*)(Bh + (size_t)n0 * K + k0), (const char*)(Bl + (size_t)n0 * K + k0)};
        const size_t grs = (size_t)K * 2;
        #pragma unroll
        for (int t = 0; t < 4; ++t) {
            #pragma unroll
            for (int i = 0; i < 2; ++i) {
                int chunk = tid + i * 256;
                int r = chunk >> 2, c = (chunk & 3) * 16;
                uint32_t dst = sbase + s * GSTG_B + t * GMAT_B + r * GROW_B + c;
                cp_async16(dst, gA[t] + (size_t)r * grs + c);
            }
        }
        cp_commit();
    };

    issue_stage(0);

    for (int it = 0; it < NIT; ++it) {
        if (it + 1 < NIT) issue_stage(it + 1);
        if (it + 1 < NIT) cp_wait<1>(); else cp_wait<0>();
        __syncthreads();

        const int s = it & 1;
        const uint32_t sA_h = sbase + s * GSTG_B + 0 * GMAT_B;
        const uint32_t sA_l = sbase + s * GSTG_B + 1 * GMAT_B;
        const uint32_t sB_h = sbase + s * GSTG_B + 2 * GMAT_B;
        const uint32_t sB_l = sbase + s * GSTG_B + 3 * GMAT_B;

        const int lg = lane >> 3;
        #pragma unroll
        for (int ks = 0; ks < 2; ++ks) {
            const int kc = ks * 16;
            uint32_t ah[4][4], al[4][4];
            #pragma unroll
            for (int mt = 0; mt < 4; ++mt) {
                uint32_t off = (uint32_t)((warp_m * 64 + mt * 16 + (lane & 7) + (lg & 1) * 8) * GROW_B
                                          + (kc + (lg >> 1) * 8) * 2);
                ldmatrix_x4(ah[mt], sA_h + off);
                ldmatrix_x4(al[mt], sA_l + off);
            }
            uint32_t bh[2][4], bl[2][4];
            #pragma unroll
            for (int p = 0; p < 2; ++p) {
                uint32_t off = (uint32_t)((warp_n * 32 + p * 16 + (lane & 7) + (lg >> 1) * 8) * GROW_B
                                          + (kc + (lg & 1) * 8) * 2);
                ldmatrix_x4(bh[p], sB_h + off);
                ldmatrix_x4(bl[p], sB_l + off);
            }
            // term-major: 16 independent mmas between same-acc reuses
            #pragma unroll
            for (int mt = 0; mt < 4; ++mt)
                #pragma unroll
                for (int nt = 0; nt < 4; ++nt)
                    mma_bf16(acc[mt][nt], ah[mt], &bh[nt >> 1][(nt & 1) * 2]);
            #pragma unroll
            for (int mt = 0; mt < 4; ++mt)
                #pragma unroll
                for (int nt = 0; nt < 4; ++nt)
                    mma_bf16(acc[mt][nt], ah[mt], &bl[nt >> 1][(nt & 1) * 2]);
            #pragma unroll
            for (int mt = 0; mt < 4; ++mt)
                #pragma unroll
                for (int nt = 0; nt < 4; ++nt)
                    mma_bf16(acc[mt][nt], al[mt], &bh[nt >> 1][(nt & 1) * 2]);
        }
        __syncthreads();
    }

    #pragma unroll
    for (int mt = 0; mt < 4; ++mt) {
        #pragma unroll
        for (int nt = 0; nt < 4; ++nt) {
            int m = m0 + warp_m * 64 + mt * 16 + (lane >> 2);
            int n = n0 + warp_n * 32 + nt * 8 + (lane & 3) * 2;
            *(float2*)&C[(size_t)m * N + n]       = make_float2(acc[mt][nt][0], acc[mt][nt][1]);
            *(float2*)&C[(size_t)(m + 8) * N + n] = make_float2(acc[mt][nt][2], acc[mt][nt][3]);
        }
    }
}

// ---------------- RoPE -----------------------------------------------------
__global__ void rope_kernel(const float* __restrict__ fcos,
                            const float* __restrict__ fsin)
{
    const int PAIRS_PER_TOK = (NHEAD + NKV) * (HD / 2);
    int idx = blockIdx.x * blockDim.x + threadIdx.x;
    if (idx >= MTOT * PAIRS_PER_TOK) return;
    int tok = idx / PAIRS_PER_TOK;
    int r = idx % PAIRS_PER_TOK;
    int t = tok % SEQ;
    int h = r / (HD / 2);
    int p = r % (HD / 2);
    float c = __ldg(&fcos[t * (HD / 2) + p]);
    float s = __ldg(&fsin[t * (HD / 2) + p]);
    float* base = &g_qkv[(size_t)tok * FDIM + h * HD + 2 * p];
    float xr = base[0], xi = base[1];
    base[0] = xr * c - xi * s;
    base[1] = xr * s + xi * c;
}

// ---------------- windowed flash attention via mma.sync bf16x3 -------------
#define AROW    136
#define AROW_B  (AROW * 2)
#define ABUF_B  (128 * AROW_B)
#define ATT_SMEM (6 * ABUF_B)

__global__ void __launch_bounds__(256) attn_mma_kernel()
{
    extern __shared__ __align__(128) char asmem[];
    const uint32_t sb  = smem_to_u32(asmem);
    const uint32_t sQh = sb,              sQl = sb + ABUF_B;
    const uint32_t sKh = sb + 2*ABUF_B,   sKl = sb + 3*ABUF_B;
    const uint32_t sVh = sb + 4*ABUF_B,   sVl = sb + 5*ABUF_B;
    __nv_bfloat16* Qh = (__nv_bfloat16*)asmem;
    __nv_bfloat16* Ql = Qh + 128*AROW;
    __nv_bfloat16* Kh = Qh + 2*128*AROW;
    __nv_bfloat16* Kl = Qh + 3*128*AROW;
    __nv_bfloat16* Vh = Qh + 4*128*AROW;
    __nv_bfloat16* Vl = Qh + 5*128*AROW;

    const int tid  = threadIdx.x;
    const int w    = tid >> 5;
    const int lane = tid & 31;
    const int lg   = lane >> 3;
    const int bh   = blockIdx.y;
    const int b    = bh / NHEAD;
    const int h    = bh % NHEAD;
    const int kvh  = h / NREP;
    const int q0   = blockIdx.x * 128;

    #pragma unroll
    for (int i = 0; i < 16; ++i) {
        int v = tid + i * 256;
        int m = v >> 5, dq = (v & 31) * 4;
        float4 q = *(const float4*)&g_qkv[(size_t)(b * SEQ + q0 + m) * FDIM + h * HD + dq];
        float f[4] = {q.x, q.y, q.z, q.w};
        #pragma unroll
        for (int e = 0; e < 4; e += 2) {
            __nv_bfloat16 h0 = __float2bfloat16(f[e]);
            __nv_bfloat16 h1 = __float2bfloat16(f[e+1]);
            float l0 = f[e]   - __bfloat162float(h0);
            float l1 = f[e+1] - __bfloat162float(h1);
            *(uint32_t*)&Qh[m * AROW + dq + e] = pack_bf16x2(__bfloat162float(h0), __bfloat162float(h1));
            *(uint32_t*)&Ql[m * AROW + dq + e] = pack_bf16x2(l0, l1);
        }
    }

    float m_i[2] = {-1e30f, -1e30f};
    float l_i[2] = {0.f, 0.f};
    float oacc[16][4];
    #pragma unroll
    for (int i = 0; i < 16; ++i)
        #pragma unroll
        for (int r = 0; r < 4; ++r) oacc[i][r] = 0.f;

    const int row_r = q0 + w * 16 + (lane >> 2);
    const int kt_lo = (q0 >= WIN) ? (q0 - WIN) : 0;

    for (int kt = kt_lo; kt <= q0; kt += 128) {
        __syncthreads();
        #pragma unroll
        for (int i = 0; i < 16; ++i) {
            int v = tid + i * 256;
            int c = v >> 5, dq = (v & 31) * 4;
            const size_t tokbase = (size_t)(b * SEQ + kt + c) * FDIM;
            float4 kk = *(const float4*)&g_qkv[tokbase + NHEAD * HD + kvh * HD + dq];
            float kf[4] = {kk.x, kk.y, kk.z, kk.w};
            #pragma unroll
            for (int e = 0; e < 4; e += 2) {
                __nv_bfloat16 h0 = __float2bfloat16(kf[e]);
                __nv_bfloat16 h1 = __float2bfloat16(kf[e+1]);
                *(uint32_t*)&Kh[c * AROW + dq + e] =
                    pack_bf16x2(__bfloat162float(h0), __bfloat162float(h1));
                *(uint32_t*)&Kl[c * AROW + dq + e] =
                    pack_bf16x2(kf[e] - __bfloat162float(h0), kf[e+1] - __bfloat162float(h1));
            }
            float4 vv = *(const float4*)&g_qkv[tokbase + (NHEAD + NKV) * HD + kvh * HD + dq];
            float vf[4] = {vv.x, vv.y, vv.z, vv.w};
            #pragma unroll
            for (int e = 0; e < 4; e += 2) {
                __nv_bfloat16 h0 = __float2bfloat16(vf[e]);
                __nv_bfloat16 h1 = __float2bfloat16(vf[e+1]);
                *(uint32_t*)&Vh[c * AROW + dq + e] =
                    pack_bf16x2(__bfloat162float(h0), __bfloat162float(h1));
                *(uint32_t*)&Vl[c * AROW + dq + e] =
                    pack_bf16x2(vf[e] - __bfloat162float(h0), vf[e+1] - __bfloat162float(h1));
            }
        }
        __syncthreads();

        float sacc[16][4];
        #pragma unroll
        for (int i = 0; i < 16; ++i)
            #pragma unroll
            for (int r = 0; r < 4; ++r) sacc[i][r] = 0.f;

        #pragma unroll
        for (int ks = 0; ks < 8; ++ks) {
            uint32_t aQh[4], aQl[4];
            uint32_t aoff = (uint32_t)((w * 16 + (lane & 7) + (lg & 1) * 8) * AROW_B
                                       + (ks * 16 + (lg >> 1) * 8) * 2);
            ldmatrix_x4(aQh, sQh + aoff);
            ldmatrix_x4(aQl, sQl + aoff);
            #pragma unroll
            for (int p16 = 0; p16 < 8; ++p16) {
                uint32_t bK[4], bKl[4];
                uint32_t boff = (uint32_t)((p16 * 16 + (lane & 7) + (lg >> 1) * 8) * AROW_B
                                           + (ks * 16 + (lg & 1) * 8) * 2);
                ldmatrix_x4(bK,  sKh + boff);
                ldmatrix_x4(bKl, sKl + boff);
                // interleaved: alternate the two accumulators / terms
                mma_bf16(sacc[2*p16],   aQh, &bK[0]);
                mma_bf16(sacc[2*p16+1], aQh, &bK[2]);
                mma_bf16(sacc[2*p16],   aQh, &bKl[0]);
                mma_bf16(sacc[2*p16+1], aQh, &bKl[2]);
                mma_bf16(sacc[2*p16],   aQl, &bK[0]);
                mma_bf16(sacc[2*p16+1], aQl, &bK[2]);
            }
        }

        #pragma unroll
        for (int nf = 0; nf < 16; ++nf) {
            int col = kt + nf * 8 + (lane & 3) * 2;
            #pragma unroll
            for (int e = 0; e < 2; ++e) {
                int cj = col + e;
                bool k0 = (cj <= row_r)     && (cj >= row_r - (WIN - 1));
                bool k1 = (cj <= row_r + 8) && (cj >= row_r + 8 - (WIN - 1));
                sacc[nf][e]     = k0 ? sacc[nf][e]     * ATT_SCALE : -1e30f;
                sacc[nf][e + 2] = k1 ? sacc[nf][e + 2] * ATT_SCALE : -1e30f;
            }
        }

        float mx0 = -1e30f, mx1 = -1e30f;
        #pragma unroll
        for (int nf = 0; nf < 16; ++nf) {
            mx0 = fmaxf(mx0, fmaxf(sacc[nf][0], sacc[nf][1]));
            mx1 = fmaxf(mx1, fmaxf(sacc[nf][2], sacc[nf][3]));
        }
        #pragma unroll
        for (int o = 1; o < 4; o <<= 1) {
            mx0 = fmaxf(mx0, __shfl_xor_sync(0xffffffffu, mx0, o));
            mx1 = fmaxf(mx1, __shfl_xor_sync(0xffffffffu, mx1, o));
        }
        float mn0 = fmaxf(m_i[0], mx0), mn1 = fmaxf(m_i[1], mx1);
        float al0 = __expf(m_i[0] - mn0), al1 = __expf(m_i[1] - mn1);
        float rs0 = 0.f, rs1 = 0.f;
        #pragma unroll
        for (int nf = 0; nf < 16; ++nf) {
            sacc[nf][0] = __expf(sacc[nf][0] - mn0);
            sacc[nf][1] = __expf(sacc[nf][1] - mn0);
            sacc[nf][2] = __expf(sacc[nf][2] - mn1);
            sacc[nf][3] = __expf(sacc[nf][3] - mn1);
            rs0 += sacc[nf][0] + sacc[nf][1];
            rs1 += sacc[nf][2] + sacc[nf][3];
        }
        #pragma unroll
        for (int o = 1; o < 4; o <<= 1) {
            rs0 += __shfl_xor_sync(0xffffffffu, rs0, o);
            rs1 += __shfl_xor_sync(0xffffffffu, rs1, o);
        }
        l_i[0] = l_i[0] * al0 + rs0;  m_i[0] = mn0;
        l_i[1] = l_i[1] * al1 + rs1;  m_i[1] = mn1;
        #pragma unroll
        for (int nf = 0; nf < 16; ++nf) {
            oacc[nf][0] *= al0; oacc[nf][1] *= al0;
            oacc[nf][2] *= al1; oacc[nf][3] *= al1;
        }

        #pragma unroll
        for (int kc = 0; kc < 8; ++kc) {
            uint32_t aph[4], apl[4];
            #pragma unroll
            for (int half = 0; half < 2; ++half) {
                const float* sf = sacc[2 * kc + half];
                __nv_bfloat16 h0 = __float2bfloat16(sf[0]);
                __nv_bfloat16 h1 = __float2bfloat16(sf[1]);
                __nv_bfloat16 h2 = __float2bfloat16(sf[2]);
                __nv_bfloat16 h3 = __float2bfloat16(sf[3]);
                aph[half * 2 + 0] = pack_bf16x2(__bfloat162float(h0), __bfloat162float(h1));
                aph[half * 2 + 1] = pack_bf16x2(__bfloat162float(h2), __bfloat162float(h3));
                apl[half * 2 + 0] = pack_bf16x2(sf[0] - __bfloat162float(h0),
                                                sf[1] - __bfloat162float(h1));
                apl[half * 2 + 1] = pack_bf16x2(sf[2] - __bfloat162float(h2),
                                                sf[3] - __bfloat162float(h3));
            }
            #pragma unroll
            for (int p16 = 0; p16 < 8; ++p16) {
                uint32_t bV[4], bVl[4];
                uint32_t boff = (uint32_t)((kc * 16 + (lane & 7) + (lg & 1) * 8) * AROW_B
                                           + (p16 * 16 + (lg >> 1) * 8) * 2);
                ldmatrix_x4_trans(bV,  sVh + boff);
                ldmatrix_x4_trans(bVl, sVl + boff);
                // interleaved accumulators / terms
                mma_bf16(oacc[2*p16],   aph, &bV[0]);
                mma_bf16(oacc[2*p16+1], aph, &bV[2]);
                mma_bf16(oacc[2*p16],   aph, &bVl[0]);
                mma_bf16(oacc[2*p16+1], aph, &bVl[2]);
                mma_bf16(oacc[2*p16],   apl, &bV[0]);
                mma_bf16(oacc[2*p16+1], apl, &bV[2]);
            }
        }
    }

    float inv0 = 1.f / l_i[0];
    float inv1 = 1.f / l_i[1];
    #pragma unroll
    for (int nf = 0; nf < 16; ++nf) {
        int d0 = nf * 8 + (lane & 3) * 2;
        size_t base0 = (size_t)(b * SEQ + row_r)     * CDIM + h * HD + d0;
        size_t base1 = (size_t)(b * SEQ + row_r + 8) * CDIM + h * HD + d0;
        float v00 = oacc[nf][0] * inv0, v01 = oacc[nf][1] * inv0;
        float v10 = oacc[nf][2] * inv1, v11 = oacc[nf][3] * inv1;
        __nv_bfloat16 h00 = __float2bfloat16(v00), h01 = __float2bfloat16(v01);
        __nv_bfloat16 h10 = __float2bfloat16(v10), h11 = __float2bfloat16(v11);
        *(uint32_t*)&g_yh[base0] = pack_bf16x2(__bfloat162float(h00), __bfloat162float(h01));
        *(uint32_t*)&g_yl[base0] = pack_bf16x2(v00 - __bfloat162float(h00),
                                               v01 - __bfloat162float(h01));
        *(uint32_t*)&g_yh[base1] = pack_bf16x2(__bfloat162float(h10), __bfloat162float(h11));
        *(uint32_t*)&g_yl[base1] = pack_bf16x2(v10 - __bfloat162float(h10),
                                               v11 - __bfloat162float(h11));
    }
}

// ---------------------------------------------------------------------------
extern "C" void kernel_launch(void* const* d_in, const int* in_sizes, int n_in,
                              void* d_out, int out_size)
{
    (void)in_sizes; (void)n_in; (void)out_size;
    const float* x      = (const float*)d_in[0];
    const float* w_qkv  = (const float*)d_in[1];
    const float* w_proj = (const float*)d_in[2];
    const float* fcos   = (const float*)d_in[3];
    const float* fsin   = (const float*)d_in[4];
    float* out = (float*)d_out;

    void *p_qkv, *p_xh, *p_xl, *p_wqh, *p_wql, *p_wph, *p_wpl, *p_yh, *p_yl;
    cudaGetSymbolAddress(&p_qkv, g_qkv);
    cudaGetSymbolAddress(&p_xh,  g_xh);
    cudaGetSymbolAddress(&p_xl,  g_xl);
    cudaGetSymbolAddress(&p_wqh, g_wqh);
    cudaGetSymbolAddress(&p_wql, g_wql);
    cudaGetSymbolAddress(&p_wph, g_wph);
    cudaGetSymbolAddress(&p_wpl, g_wpl);
    cudaGetSymbolAddress(&p_yh,  g_yh);
    cudaGetSymbolAddress(&p_yl,  g_yl);

    cudaFuncSetAttribute(gemm_bf16x3_kernel,
                         cudaFuncAttributeMaxDynamicSharedMemorySize, GEMM_SMEM);
    cudaFuncSetAttribute(attn_mma_kernel,
                         cudaFuncAttributeMaxDynamicSharedMemorySize, ATT_SMEM);

    // splits
    {
        int n = MTOT * CDIM;
        split_kernel<<<(n + 255) / 256, 256>>>(x, (__nv_bfloat16*)p_xh, (__nv_bfloat16*)p_xl, n);
        n = FDIM * CDIM;
        split_kernel<<<(n + 255) / 256, 256>>>(w_qkv, (__nv_bfloat16*)p_wqh, (__nv_bfloat16*)p_wql, n);
        n = CDIM * CDIM;
        split_kernel<<<(n + 255) / 256, 256>>>(w_proj, (__nv_bfloat16*)p_wph, (__nv_bfloat16*)p_wpl, n);
    }
    // QKV projection
    {
        dim3 grid(FDIM / 128, MTOT / 128);
        gemm_bf16x3_kernel<<<grid, 256, GEMM_SMEM>>>(
            (const __nv_bfloat16*)p_xh, (const __nv_bfloat16*)p_xl,
            (const __nv_bfloat16*)p_wqh, (const __nv_bfloat16*)p_wql,
            (float*)p_qkv, MTOT, FDIM, CDIM);
    }
    // RoPE
    {
        int total = MTOT * (NHEAD + NKV) * (HD / 2);
        rope_kernel<<<(total + 255) / 256, 256>>>(fcos, fsin);
    }
    // Attention
    {
        dim3 grid(SEQ / 128, BATCH * NHEAD);
        attn_mma_kernel<<<grid, 256, ATT_SMEM>>>();
    }
    // Output projection
    {
        dim3 grid(CDIM / 128, MTOT / 128);
        gemm_bf16x3_kernel<<<grid, 256, GEMM_SMEM>>>(
            (const __nv_bfloat16*)p_yh, (const __nv_bfloat16*)p_yl,
            (const __nv_bfloat16*)p_wph, (const __nv_bfloat16*)p_wpl,
            out, MTOT, CDIM, CDIM);
    }
}

// round 12
// speedup vs baseline: 1.5886x; 1.4158x over previous
#include <cuda_runtime.h>
#include <cuda_fp16.h>
#include <cstdint>
#include <math.h>

#define BATCH 2
#define SEQ   2048
#define CDIM  2048
#define NHEAD 16
#define NKV   4
#define HD    128
#define NREP  4
#define WIN   512
#define FDIM  3072
#define MTOT  (BATCH*SEQ)   // 4096
#define ATT_SCALE 0.08838834764831845f

// ---------------- scratch (__device__ globals; no allocations) -------------
__device__ float  g_qkv[(size_t)MTOT * FDIM];
__device__ __half g_xh[(size_t)MTOT * CDIM];
__device__ __half g_xl[(size_t)MTOT * CDIM];
__device__ __half g_wq[(size_t)FDIM * CDIM];
__device__ __half g_wp[(size_t)CDIM * CDIM];
__device__ __half g_yh[(size_t)MTOT * CDIM];
__device__ __half g_yl[(size_t)MTOT * CDIM];

// ---------------- helpers --------------------------------------------------
__device__ __forceinline__ uint32_t smem_to_u32(const void* p) {
    uint32_t a;
    asm("{ .reg .u64 t; cvta.to.shared.u64 t, %1; cvt.u32.u64 %0, t; }" : "=r"(a) : "l"(p));
    return a;
}
__device__ __forceinline__ void cp_async16(uint32_t dst, const void* src) {
    asm volatile("cp.async.cg.shared.global [%0], [%1], 16;" :: "r"(dst), "l"(src));
}
__device__ __forceinline__ void cp_commit() {
    asm volatile("cp.async.commit_group;");
}
template <int N>
__device__ __forceinline__ void cp_wait() {
    asm volatile("cp.async.wait_group %0;" :: "n"(N));
}
__device__ __forceinline__ void ldmatrix_x4(uint32_t* r, uint32_t addr) {
    asm volatile("ldmatrix.sync.aligned.m8n8.x4.shared.b16 {%0,%1,%2,%3}, [%4];"
        : "=r"(r[0]), "=r"(r[1]), "=r"(r[2]), "=r"(r[3]) : "r"(addr));
}
__device__ __forceinline__ void ldmatrix_x4_trans(uint32_t* r, uint32_t addr) {
    asm volatile("ldmatrix.sync.aligned.m8n8.x4.trans.shared.b16 {%0,%1,%2,%3}, [%4];"
        : "=r"(r[0]), "=r"(r[1]), "=r"(r[2]), "=r"(r[3]) : "r"(addr));
}
__device__ __forceinline__ void mma_fp16(float* c, const uint32_t* a, const uint32_t* b) {
    asm volatile(
        "mma.sync.aligned.m16n8k16.row.col.f32.f16.f16.f32 "
        "{%0,%1,%2,%3}, {%4,%5,%6,%7}, {%8,%9}, {%0,%1,%2,%3};"
        : "+f"(c[0]), "+f"(c[1]), "+f"(c[2]), "+f"(c[3])
        : "r"(a[0]), "r"(a[1]), "r"(a[2]), "r"(a[3]), "r"(b[0]), "r"(b[1]));
}
__device__ __forceinline__ uint32_t pack_half2(float lo, float hi) {
    __half2 t = __floats2half2_rn(lo, hi);
    return *(uint32_t*)&t;
}

// ---------------- splits ---------------------------------------------------
__global__ void split2_kernel(const float* __restrict__ src,
                              __half* __restrict__ hi,
                              __half* __restrict__ lo, int n)
{
    int i = blockIdx.x * blockDim.x + threadIdx.x;
    if (i >= n) return;
    float v = src[i];
    __half h = __float2half_rn(v);
    hi[i] = h;
    lo[i] = __float2half_rn(v - __half2float(h));
}
__global__ void convert_kernel(const float* __restrict__ src,
                               __half* __restrict__ dst, int n)
{
    int i = blockIdx.x * blockDim.x + threadIdx.x;
    if (i >= n) return;
    dst[i] = __float2half_rn(src[i]);
}

// ---------------- fp16x2 NT GEMM: C = (Ah+Al) * Bh^T -----------------------
// CTA 128x128, BK=32, 2-stage cp.async (proven 2 CTAs/SM shape).
#define GPAD     40
#define GROW_B   (GPAD * 2)
#define GMAT_B   (128 * GROW_B)
#define GSTG_B   (3 * GMAT_B)          // Ah, Al, Bh = 30720
#define GEMM_SMEM (2 * GSTG_B)         // 61440 -> 2 CTAs/SM

__global__ void __launch_bounds__(256)
gemm_fp16x2_kernel(const __half* __restrict__ Ah, const __half* __restrict__ Al,
                   const __half* __restrict__ Bh,
                   float* __restrict__ C, int M, int N, int K)
{
    extern __shared__ __align__(128) char smem[];
    const uint32_t sbase = smem_to_u32(smem);

    const int tid  = threadIdx.x;
    const int wid  = tid >> 5;
    const int lane = tid & 31;
    const int warp_m = wid & 1;
    const int warp_n = wid >> 1;
    const int m0 = blockIdx.y * 128;
    const int n0 = blockIdx.x * 128;

    float acc[4][4][4];
    #pragma unroll
    for (int i = 0; i < 4; ++i)
        #pragma unroll
        for (int j = 0; j < 4; ++j)
            #pragma unroll
            for (int r = 0; r < 4; ++r) acc[i][j][r] = 0.f;

    const int NIT = K >> 5;

    auto issue_stage = [&](int it) {
        const int s = it & 1;
        const int k0 = it * 32;
        const char* gA[3] = {
            (const char*)(Ah + (size_t)m0 * K + k0), (const char*)(Al + (size_t)m0 * K + k0),
            (const char*)(Bh + (size_t)n0 * K + k0)};
        const size_t grs = (size_t)K * 2;
        #pragma unroll
        for (int t = 0; t < 3; ++t) {
            #pragma unroll
            for (int i = 0; i < 2; ++i) {
                int chunk = tid + i * 256;
                int r = chunk >> 2, c = (chunk & 3) * 16;
                uint32_t dst = sbase + s * GSTG_B + t * GMAT_B + r * GROW_B + c;
                cp_async16(dst, gA[t] + (size_t)r * grs + c);
            }
        }
        cp_commit();
    };

    issue_stage(0);

    for (int it = 0; it < NIT; ++it) {
        if (it + 1 < NIT) issue_stage(it + 1);
        if (it + 1 < NIT) cp_wait<1>(); else cp_wait<0>();
        __syncthreads();

        const int s = it & 1;
        const uint32_t sA_h = sbase + s * GSTG_B + 0 * GMAT_B;
        const uint32_t sA_l = sbase + s * GSTG_B + 1 * GMAT_B;
        const uint32_t sB_h = sbase + s * GSTG_B + 2 * GMAT_B;

        const int lg = lane >> 3;
        #pragma unroll
        for (int ks = 0; ks < 2; ++ks) {
            const int kc = ks * 16;
            uint32_t ah[4][4], al[4][4];
            #pragma unroll
            for (int mt = 0; mt < 4; ++mt) {
                uint32_t off = (uint32_t)((warp_m * 64 + mt * 16 + (lane & 7) + (lg & 1) * 8) * GROW_B
                                          + (kc + (lg >> 1) * 8) * 2);
                ldmatrix_x4(ah[mt], sA_h + off);
                ldmatrix_x4(al[mt], sA_l + off);
            }
            uint32_t bh[2][4];
            #pragma unroll
            for (int p = 0; p < 2; ++p) {
                uint32_t off = (uint32_t)((warp_n * 32 + p * 16 + (lane & 7) + (lg >> 1) * 8) * GROW_B
                                          + (kc + (lg & 1) * 8) * 2);
                ldmatrix_x4(bh[p], sB_h + off);
            }
            #pragma unroll
            for (int mt = 0; mt < 4; ++mt)
                #pragma unroll
                for (int nt = 0; nt < 4; ++nt)
                    mma_fp16(acc[mt][nt], ah[mt], &bh[nt >> 1][(nt & 1) * 2]);
            #pragma unroll
            for (int mt = 0; mt < 4; ++mt)
                #pragma unroll
                for (int nt = 0; nt < 4; ++nt)
                    mma_fp16(acc[mt][nt], al[mt], &bh[nt >> 1][(nt & 1) * 2]);
        }
        __syncthreads();
    }

    #pragma unroll
    for (int mt = 0; mt < 4; ++mt) {
        #pragma unroll
        for (int nt = 0; nt < 4; ++nt) {
            int m = m0 + warp_m * 64 + mt * 16 + (lane >> 2);
            int n = n0 + warp_n * 32 + nt * 8 + (lane & 3) * 2;
            *(float2*)&C[(size_t)m * N + n]       = make_float2(acc[mt][nt][0], acc[mt][nt][1]);
            *(float2*)&C[(size_t)(m + 8) * N + n] = make_float2(acc[mt][nt][2], acc[mt][nt][3]);
        }
    }
}

// ---------------- RoPE -----------------------------------------------------
__global__ void rope_kernel(const float* __restrict__ fcos,
                            const float* __restrict__ fsin)
{
    const int PAIRS_PER_TOK = (NHEAD + NKV) * (HD / 2);
    int idx = blockIdx.x * blockDim.x + threadIdx.x;
    if (idx >= MTOT * PAIRS_PER_TOK) return;
    int tok = idx / PAIRS_PER_TOK;
    int r = idx % PAIRS_PER_TOK;
    int t = tok % SEQ;
    int h = r / (HD / 2);
    int p = r % (HD / 2);
    float c = __ldg(&fcos[t * (HD / 2) + p]);
    float s = __ldg(&fsin[t * (HD / 2) + p]);
    float* base = &g_qkv[(size_t)tok * FDIM + h * HD + 2 * p];
    float xr = base[0], xi = base[1];
    base[0] = xr * c - xi * s;
    base[1] = xr * s + xi * c;
}

// ---------------- windowed flash attention via mma.sync fp16x2 -------------
// Q split (Qh+Ql) x K single; P split (Ph+Pl) x V single.
#define AROW    136
#define AROW_B  (AROW * 2)
#define ABUF_B  (128 * AROW_B)
#define ATT_SMEM (4 * ABUF_B)          // Qh, Ql, K, V = 139264

__global__ void __launch_bounds__(256) attn_mma_kernel()
{
    extern __shared__ __align__(128) char asmem[];
    const uint32_t sb  = smem_to_u32(asmem);
    const uint32_t sQh = sb,              sQl = sb + ABUF_B;
    const uint32_t sK  = sb + 2*ABUF_B,   sV  = sb + 3*ABUF_B;
    __half* Qh = (__half*)asmem;
    __half* Ql = Qh + 128*AROW;
    __half* Kt = Qh + 2*128*AROW;
    __half* Vt = Qh + 3*128*AROW;

    const int tid  = threadIdx.x;
    const int w    = tid >> 5;
    const int lane = tid & 31;
    const int lg   = lane >> 3;
    const int bh   = blockIdx.y;
    const int b    = bh / NHEAD;
    const int h    = bh % NHEAD;
    const int kvh  = h / NREP;
    const int q0   = blockIdx.x * 128;

    // ---- load Q tile, split hi/lo fp16 ----
    #pragma unroll
    for (int i = 0; i < 16; ++i) {
        int v = tid + i * 256;
        int m = v >> 5, dq = (v & 31) * 4;
        float4 q = *(const float4*)&g_qkv[(size_t)(b * SEQ + q0 + m) * FDIM + h * HD + dq];
        float f[4] = {q.x, q.y, q.z, q.w};
        #pragma unroll
        for (int e = 0; e < 4; e += 2) {
            __half h0 = __float2half_rn(f[e]);
            __half h1 = __float2half_rn(f[e+1]);
            *(uint32_t*)&Qh[m * AROW + dq + e] = pack_half2(__half2float(h0), __half2float(h1));
            *(uint32_t*)&Ql[m * AROW + dq + e] = pack_half2(f[e]   - __half2float(h0),
                                                            f[e+1] - __half2float(h1));
        }
    }

    float m_i[2] = {-1e30f, -1e30f};
    float l_i[2] = {0.f, 0.f};
    float oacc[16][4];
    #pragma unroll
    for (int i = 0; i < 16; ++i)
        #pragma unroll
        for (int r = 0; r < 4; ++r) oacc[i][r] = 0.f;

    const int row_r = q0 + w * 16 + (lane >> 2);
    const int kt_lo = (q0 >= WIN) ? (q0 - WIN) : 0;

    for (int kt = kt_lo; kt <= q0; kt += 128) {
        __syncthreads();
        // ---- load K, V tiles (single fp16, row=token, col=dim) ----
        #pragma unroll
        for (int i = 0; i < 16; ++i) {
            int v = tid + i * 256;
            int c = v >> 5, dq = (v & 31) * 4;
            const size_t tokbase = (size_t)(b * SEQ + kt + c) * FDIM;
            float4 kk = *(const float4*)&g_qkv[tokbase + NHEAD * HD + kvh * HD + dq];
            *(uint32_t*)&Kt[c * AROW + dq]     = pack_half2(kk.x, kk.y);
            *(uint32_t*)&Kt[c * AROW + dq + 2] = pack_half2(kk.z, kk.w);
            float4 vv = *(const float4*)&g_qkv[tokbase + (NHEAD + NKV) * HD + kvh * HD + dq];
            *(uint32_t*)&Vt[c * AROW + dq]     = pack_half2(vv.x, vv.y);
            *(uint32_t*)&Vt[c * AROW + dq + 2] = pack_half2(vv.z, vv.w);
        }
        __syncthreads();

        // ---- S = Q K^T (2-term fp16) ----
        float sacc[16][4];
        #pragma unroll
        for (int i = 0; i < 16; ++i)
            #pragma unroll
            for (int r = 0; r < 4; ++r) sacc[i][r] = 0.f;

        #pragma unroll
        for (int ks = 0; ks < 8; ++ks) {
            uint32_t aQh[4], aQl[4];
            uint32_t aoff = (uint32_t)((w * 16 + (lane & 7) + (lg & 1) * 8) * AROW_B
                                       + (ks * 16 + (lg >> 1) * 8) * 2);
            ldmatrix_x4(aQh, sQh + aoff);
            ldmatrix_x4(aQl, sQl + aoff);
            #pragma unroll
            for (int p16 = 0; p16 < 8; ++p16) {
                uint32_t bK[4];
                uint32_t boff = (uint32_t)((p16 * 16 + (lane & 7) + (lg >> 1) * 8) * AROW_B
                                           + (ks * 16 + (lg & 1) * 8) * 2);
                ldmatrix_x4(bK, sK + boff);
                mma_fp16(sacc[2*p16],   aQh, &bK[0]);
                mma_fp16(sacc[2*p16+1], aQh, &bK[2]);
                mma_fp16(sacc[2*p16],   aQl, &bK[0]);
                mma_fp16(sacc[2*p16+1], aQl, &bK[2]);
            }
        }

        // ---- mask + scale ----
        #pragma unroll
        for (int nf = 0; nf < 16; ++nf) {
            int col = kt + nf * 8 + (lane & 3) * 2;
            #pragma unroll
            for (int e = 0; e < 2; ++e) {
                int cj = col + e;
                bool k0 = (cj <= row_r)     && (cj >= row_r - (WIN - 1));
                bool k1 = (cj <= row_r + 8) && (cj >= row_r + 8 - (WIN - 1));
                sacc[nf][e]     = k0 ? sacc[nf][e]     * ATT_SCALE : -1e30f;
                sacc[nf][e + 2] = k1 ? sacc[nf][e + 2] * ATT_SCALE : -1e30f;
            }
        }

        // ---- online softmax ----
        float mx0 = -1e30f, mx1 = -1e30f;
        #pragma unroll
        for (int nf = 0; nf < 16; ++nf) {
            mx0 = fmaxf(mx0, fmaxf(sacc[nf][0], sacc[nf][1]));
            mx1 = fmaxf(mx1, fmaxf(sacc[nf][2], sacc[nf][3]));
        }
        #pragma unroll
        for (int o = 1; o < 4; o <<= 1) {
            mx0 = fmaxf(mx0, __shfl_xor_sync(0xffffffffu, mx0, o));
            mx1 = fmaxf(mx1, __shfl_xor_sync(0xffffffffu, mx1, o));
        }
        float mn0 = fmaxf(m_i[0], mx0), mn1 = fmaxf(m_i[1], mx1);
        float al0 = __expf(m_i[0] - mn0), al1 = __expf(m_i[1] - mn1);
        float rs0 = 0.f, rs1 = 0.f;
        #pragma unroll
        for (int nf = 0; nf < 16; ++nf) {
            sacc[nf][0] = __expf(sacc[nf][0] - mn0);
            sacc[nf][1] = __expf(sacc[nf][1] - mn0);
            sacc[nf][2] = __expf(sacc[nf][2] - mn1);
            sacc[nf][3] = __expf(sacc[nf][3] - mn1);
            rs0 += sacc[nf][0] + sacc[nf][1];
            rs1 += sacc[nf][2] + sacc[nf][3];
        }
        #pragma unroll
        for (int o = 1; o < 4; o <<= 1) {
            rs0 += __shfl_xor_sync(0xffffffffu, rs0, o);
            rs1 += __shfl_xor_sync(0xffffffffu, rs1, o);
        }
        l_i[0] = l_i[0] * al0 + rs0;  m_i[0] = mn0;
        l_i[1] = l_i[1] * al1 + rs1;  m_i[1] = mn1;
        #pragma unroll
        for (int nf = 0; nf < 16; ++nf) {
            oacc[nf][0] *= al0; oacc[nf][1] *= al0;
            oacc[nf][2] *= al1; oacc[nf][3] *= al1;
        }

        // ---- O += P V (2-term: P split fp16, V single) ----
        #pragma unroll
        for (int kc = 0; kc < 8; ++kc) {
            uint32_t aph[4], apl[4];
            #pragma unroll
            for (int half = 0; half < 2; ++half) {
                const float* sf = sacc[2 * kc + half];
                __half h0 = __float2half_rn(sf[0]);
                __half h1 = __float2half_rn(sf[1]);
                __half h2 = __float2half_rn(sf[2]);
                __half h3 = __float2half_rn(sf[3]);
                aph[half * 2 + 0] = pack_half2(__half2float(h0), __half2float(h1));
                aph[half * 2 + 1] = pack_half2(__half2float(h2), __half2float(h3));
                apl[half * 2 + 0] = pack_half2(sf[0] - __half2float(h0),
                                               sf[1] - __half2float(h1));
                apl[half * 2 + 1] = pack_half2(sf[2] - __half2float(h2),
                                               sf[3] - __half2float(h3));
            }
            #pragma unroll
            for (int p16 = 0; p16 < 8; ++p16) {
                uint32_t bV[4];
                uint32_t boff = (uint32_t)((kc * 16 + (lane & 7) + (lg & 1) * 8) * AROW_B
                                           + (p16 * 16 + (lg >> 1) * 8) * 2);
                ldmatrix_x4_trans(bV, sV + boff);
                mma_fp16(oacc[2*p16],   aph, &bV[0]);
                mma_fp16(oacc[2*p16+1], aph, &bV[2]);
                mma_fp16(oacc[2*p16],   apl, &bV[0]);
                mma_fp16(oacc[2*p16+1], apl, &bV[2]);
            }
        }
    }

    // ---- normalize, split hi/lo fp16, write y ----
    float inv0 = 1.f / l_i[0];
    float inv1 = 1.f / l_i[1];
    #pragma unroll
    for (int nf = 0; nf < 16; ++nf) {
        int d0 = nf * 8 + (lane & 3) * 2;
        size_t base0 = (size_t)(b * SEQ + row_r)     * CDIM + h * HD + d0;
        size_t base1 = (size_t)(b * SEQ + row_r + 8) * CDIM + h * HD + d0;
        float v00 = oacc[nf][0] * inv0, v01 = oacc[nf][1] * inv0;
        float v10 = oacc[nf][2] * inv1, v11 = oacc[nf][3] * inv1;
        __half h00 = __float2half_rn(v00), h01 = __float2half_rn(v01);
        __half h10 = __float2half_rn(v10), h11 = __float2half_rn(v11);
        *(uint32_t*)&g_yh[base0] = pack_half2(__half2float(h00), __half2float(h01));
        *(uint32_t*)&g_yl[base0] = pack_half2(v00 - __half2float(h00),
                                              v01 - __half2float(h01));
        *(uint32_t*)&g_yh[base1] = pack_half2(__half2float(h10), __half2float(h11));
        *(uint32_t*)&g_yl[base1] = pack_half2(v10 - __half2float(h10),
                                              v11 - __half2float(h11));
    }
}

// ---------------------------------------------------------------------------
extern "C" void kernel_launch(void* const* d_in, const int* in_sizes, int n_in,
                              void* d_out, int out_size)
{
    (void)in_sizes; (void)n_in; (void)out_size;
    const float* x      = (const float*)d_in[0];
    const float* w_qkv  = (const float*)d_in[1];
    const float* w_proj = (const float*)d_in[2];
    const float* fcos   = (const float*)d_in[3];
    const float* fsin   = (const float*)d_in[4];
    float* out = (float*)d_out;

    void *p_qkv, *p_xh, *p_xl, *p_wq, *p_wp, *p_yh, *p_yl;
    cudaGetSymbolAddress(&p_qkv, g_qkv);
    cudaGetSymbolAddress(&p_xh,  g_xh);
    cudaGetSymbolAddress(&p_xl,  g_xl);
    cudaGetSymbolAddress(&p_wq,  g_wq);
    cudaGetSymbolAddress(&p_wp,  g_wp);
    cudaGetSymbolAddress(&p_yh,  g_yh);
    cudaGetSymbolAddress(&p_yl,  g_yl);

    cudaFuncSetAttribute(gemm_fp16x2_kernel,
                         cudaFuncAttributeMaxDynamicSharedMemorySize, GEMM_SMEM);
    cudaFuncSetAttribute(attn_mma_kernel,
                         cudaFuncAttributeMaxDynamicSharedMemorySize, ATT_SMEM);

    // splits / converts
    {
        int n = MTOT * CDIM;
        split2_kernel<<<(n + 255) / 256, 256>>>(x, (__half*)p_xh, (__half*)p_xl, n);
        n = FDIM * CDIM;
        convert_kernel<<<(n + 255) / 256, 256>>>(w_qkv, (__half*)p_wq, n);
        n = CDIM * CDIM;
        convert_kernel<<<(n + 255) / 256, 256>>>(w_proj, (__half*)p_wp, n);
    }
    // QKV projection
    {
        dim3 grid(FDIM / 128, MTOT / 128);
        gemm_fp16x2_kernel<<<grid, 256, GEMM_SMEM>>>(
            (const __half*)p_xh, (const __half*)p_xl, (const __half*)p_wq,
            (float*)p_qkv, MTOT, FDIM, CDIM);
    }
    // RoPE
    {
        int total = MTOT * (NHEAD + NKV) * (HD / 2);
        rope_kernel<<<(total + 255) / 256, 256>>>(fcos, fsin);
    }
    // Attention
    {
        dim3 grid(SEQ / 128, BATCH * NHEAD);
        attn_mma_kernel<<<grid, 256, ATT_SMEM>>>();
    }
    // Output projection
    {
        dim3 grid(CDIM / 128, MTOT / 128);
        gemm_fp16x2_kernel<<<grid, 256, GEMM_SMEM>>>(
            (const __half*)p_yh, (const __half*)p_yl, (const __half*)p_wp,
            out, MTOT, CDIM, CDIM);
    }
}

// round 13
// speedup vs baseline: 1.5893x; 1.0004x over previous
#include <cuda_runtime.h>
#include <cuda_fp16.h>
#include <cstdint>
#include <math.h>

#define BATCH 2
#define SEQ   2048
#define CDIM  2048
#define NHEAD 16
#define NKV   4
#define HD    128
#define NREP  4
#define WIN   512
#define FDIM  3072
#define MTOT  (BATCH*SEQ)   // 4096
#define ATT_SCALE 0.08838834764831845f

// ---------------- scratch (__device__ globals; no allocations) -------------
__device__ float  g_qkv[(size_t)MTOT * FDIM];
__device__ __half g_xh[(size_t)MTOT * CDIM];
__device__ __half g_xl[(size_t)MTOT * CDIM];
__device__ __half g_wq[(size_t)FDIM * CDIM];
__device__ __half g_wp[(size_t)CDIM * CDIM];
__device__ __half g_yh[(size_t)MTOT * CDIM];
__device__ __half g_yl[(size_t)MTOT * CDIM];

// ---------------- helpers --------------------------------------------------
__device__ __forceinline__ uint32_t smem_to_u32(const void* p) {
    uint32_t a;
    asm("{ .reg .u64 t; cvta.to.shared.u64 t, %1; cvt.u32.u64 %0, t; }" : "=r"(a) : "l"(p));
    return a;
}
__device__ __forceinline__ void cp_async16(uint32_t dst, const void* src) {
    asm volatile("cp.async.cg.shared.global [%0], [%1], 16;" :: "r"(dst), "l"(src));
}
__device__ __forceinline__ void cp_commit() {
    asm volatile("cp.async.commit_group;");
}
template <int N>
__device__ __forceinline__ void cp_wait() {
    asm volatile("cp.async.wait_group %0;" :: "n"(N));
}
__device__ __forceinline__ void ldmatrix_x4(uint32_t* r, uint32_t addr) {
    asm volatile("ldmatrix.sync.aligned.m8n8.x4.shared.b16 {%0,%1,%2,%3}, [%4];"
        : "=r"(r[0]), "=r"(r[1]), "=r"(r[2]), "=r"(r[3]) : "r"(addr));
}
__device__ __forceinline__ void ldmatrix_x4_trans(uint32_t* r, uint32_t addr) {
    asm volatile("ldmatrix.sync.aligned.m8n8.x4.trans.shared.b16 {%0,%1,%2,%3}, [%4];"
        : "=r"(r[0]), "=r"(r[1]), "=r"(r[2]), "=r"(r[3]) : "r"(addr));
}
__device__ __forceinline__ void mma_fp16(float* c, const uint32_t* a, const uint32_t* b) {
    asm volatile(
        "mma.sync.aligned.m16n8k16.row.col.f32.f16.f16.f32 "
        "{%0,%1,%2,%3}, {%4,%5,%6,%7}, {%8,%9}, {%0,%1,%2,%3};"
        : "+f"(c[0]), "+f"(c[1]), "+f"(c[2]), "+f"(c[3])
        : "r"(a[0]), "r"(a[1]), "r"(a[2]), "r"(a[3]), "r"(b[0]), "r"(b[1]));
}
__device__ __forceinline__ uint32_t pack_half2(float lo, float hi) {
    __half2 t = __floats2half2_rn(lo, hi);
    return *(uint32_t*)&t;
}

// ---------------- splits ---------------------------------------------------
__global__ void split2_kernel(const float* __restrict__ src,
                              __half* __restrict__ hi,
                              __half* __restrict__ lo, int n)
{
    int i = blockIdx.x * blockDim.x + threadIdx.x;
    if (i >= n) return;
    float v = src[i];
    __half h = __float2half_rn(v);
    hi[i] = h;
    lo[i] = __float2half_rn(v - __half2float(h));
}
__global__ void convert_kernel(const float* __restrict__ src,
                               __half* __restrict__ dst, int n)
{
    int i = blockIdx.x * blockDim.x + threadIdx.x;
    if (i >= n) return;
    dst[i] = __float2half_rn(src[i]);
}

// ---------------- fp16x2 NT GEMM: C = (Ah+Al) * Bh^T -----------------------
// CTA 128x128, BK=32, 2-stage cp.async, ONE barrier per K-iter.
#define GPAD     40
#define GROW_B   (GPAD * 2)
#define GMAT_B   (128 * GROW_B)
#define GSTG_B   (3 * GMAT_B)          // Ah, Al, Bh = 30720
#define GEMM_SMEM (2 * GSTG_B)         // 61440 -> 2 CTAs/SM

__global__ void __launch_bounds__(256)
gemm_fp16x2_kernel(const __half* __restrict__ Ah, const __half* __restrict__ Al,
                   const __half* __restrict__ Bh,
                   float* __restrict__ C, int M, int N, int K)
{
    extern __shared__ __align__(128) char smem[];
    const uint32_t sbase = smem_to_u32(smem);

    const int tid  = threadIdx.x;
    const int wid  = tid >> 5;
    const int lane = tid & 31;
    const int warp_m = wid & 1;
    const int warp_n = wid >> 1;
    const int m0 = blockIdx.y * 128;
    const int n0 = blockIdx.x * 128;

    float acc[4][4][4];
    #pragma unroll
    for (int i = 0; i < 4; ++i)
        #pragma unroll
        for (int j = 0; j < 4; ++j)
            #pragma unroll
            for (int r = 0; r < 4; ++r) acc[i][j][r] = 0.f;

    const int NIT = K >> 5;

    auto issue_stage = [&](int it) {
        const int s = it & 1;
        const int k0 = it * 32;
        const char* gA[3] = {
            (const char*)(Ah + (size_t)m0 * K + k0), (const char*)(Al + (size_t)m0 * K + k0),
            (const char*)(Bh + (size_t)n0 * K + k0)};
        const size_t grs = (size_t)K * 2;
        #pragma unroll
        for (int t = 0; t < 3; ++t) {
            #pragma unroll
            for (int i = 0; i < 2; ++i) {
                int chunk = tid + i * 256;
                int r = chunk >> 2, c = (chunk & 3) * 16;
                uint32_t dst = sbase + s * GSTG_B + t * GMAT_B + r * GROW_B + c;
                cp_async16(dst, gA[t] + (size_t)r * grs + c);
            }
        }
        cp_commit();
    };

    issue_stage(0);

    for (int it = 0; it < NIT; ++it) {
        cp_wait<0>();          // stage `it` resident for this thread
        __syncthreads();       // all warps done with prior slot's reads + data visible
        if (it + 1 < NIT) issue_stage(it + 1);   // writes the OTHER slot — safe

        const int s = it & 1;
        const uint32_t sA_h = sbase + s * GSTG_B + 0 * GMAT_B;
        const uint32_t sA_l = sbase + s * GSTG_B + 1 * GMAT_B;
        const uint32_t sB_h = sbase + s * GSTG_B + 2 * GMAT_B;

        const int lg = lane >> 3;
        #pragma unroll
        for (int ks = 0; ks < 2; ++ks) {
            const int kc = ks * 16;
            uint32_t ah[4][4], al[4][4];
            #pragma unroll
            for (int mt = 0; mt < 4; ++mt) {
                uint32_t off = (uint32_t)((warp_m * 64 + mt * 16 + (lane & 7) + (lg & 1) * 8) * GROW_B
                                          + (kc + (lg >> 1) * 8) * 2);
                ldmatrix_x4(ah[mt], sA_h + off);
                ldmatrix_x4(al[mt], sA_l + off);
            }
            uint32_t bh[2][4];
            #pragma unroll
            for (int p = 0; p < 2; ++p) {
                uint32_t off = (uint32_t)((warp_n * 32 + p * 16 + (lane & 7) + (lg >> 1) * 8) * GROW_B
                                          + (kc + (lg & 1) * 8) * 2);
                ldmatrix_x4(bh[p], sB_h + off);
            }
            #pragma unroll
            for (int mt = 0; mt < 4; ++mt)
                #pragma unroll
                for (int nt = 0; nt < 4; ++nt)
                    mma_fp16(acc[mt][nt], ah[mt], &bh[nt >> 1][(nt & 1) * 2]);
            #pragma unroll
            for (int mt = 0; mt < 4; ++mt)
                #pragma unroll
                for (int nt = 0; nt < 4; ++nt)
                    mma_fp16(acc[mt][nt], al[mt], &bh[nt >> 1][(nt & 1) * 2]);
        }
    }

    #pragma unroll
    for (int mt = 0; mt < 4; ++mt) {
        #pragma unroll
        for (int nt = 0; nt < 4; ++nt) {
            int m = m0 + warp_m * 64 + mt * 16 + (lane >> 2);
            int n = n0 + warp_n * 32 + nt * 8 + (lane & 3) * 2;
            *(float2*)&C[(size_t)m * N + n]       = make_float2(acc[mt][nt][0], acc[mt][nt][1]);
            *(float2*)&C[(size_t)(m + 8) * N + n] = make_float2(acc[mt][nt][2], acc[mt][nt][3]);
        }
    }
}

// ---------------- windowed flash attention, RoPE fused into Q/K load -------
#define AROW    136
#define AROW_B  (AROW * 2)
#define ABUF_B  (128 * AROW_B)
#define ATT_SMEM (4 * ABUF_B)          // Qh, Ql, K, V = 139264

__global__ void __launch_bounds__(256) attn_mma_kernel(
    const float* __restrict__ fcos, const float* __restrict__ fsin)
{
    extern __shared__ __align__(128) char asmem[];
    const uint32_t sb  = smem_to_u32(asmem);
    const uint32_t sQh = sb,              sQl = sb + ABUF_B;
    const uint32_t sK  = sb + 2*ABUF_B,   sV  = sb + 3*ABUF_B;
    __half* Qh = (__half*)asmem;
    __half* Ql = Qh + 128*AROW;
    __half* Kt = Qh + 2*128*AROW;
    __half* Vt = Qh + 3*128*AROW;

    const int tid  = threadIdx.x;
    const int w    = tid >> 5;
    const int lane = tid & 31;
    const int lg   = lane >> 3;
    const int bh   = blockIdx.y;
    const int b    = bh / NHEAD;
    const int h    = bh % NHEAD;
    const int kvh  = h / NREP;
    const int q0   = blockIdx.x * 128;

    // ---- load Q tile, apply RoPE (fp32), split hi/lo fp16 ----
    #pragma unroll
    for (int i = 0; i < 16; ++i) {
        int v = tid + i * 256;
        int m = v >> 5, dq = (v & 31) * 4;
        int t = q0 + m;
        float4 q = *(const float4*)&g_qkv[(size_t)(b * SEQ + t) * FDIM + h * HD + dq];
        int p0 = dq >> 1;                       // dq multiple of 4 -> pairs (x,y),(z,w)
        float c0 = __ldg(&fcos[t * (HD/2) + p0]),     s0 = __ldg(&fsin[t * (HD/2) + p0]);
        float c1 = __ldg(&fcos[t * (HD/2) + p0 + 1]), s1 = __ldg(&fsin[t * (HD/2) + p0 + 1]);
        float f[4];
        f[0] = q.x * c0 - q.y * s0;  f[1] = q.x * s0 + q.y * c0;
        f[2] = q.z * c1 - q.w * s1;  f[3] = q.z * s1 + q.w * c1;
        #pragma unroll
        for (int e = 0; e < 4; e += 2) {
            __half h0 = __float2half_rn(f[e]);
            __half h1 = __float2half_rn(f[e+1]);
            *(uint32_t*)&Qh[m * AROW + dq + e] = pack_half2(__half2float(h0), __half2float(h1));
            *(uint32_t*)&Ql[m * AROW + dq + e] = pack_half2(f[e]   - __half2float(h0),
                                                            f[e+1] - __half2float(h1));
        }
    }

    float m_i[2] = {-1e30f, -1e30f};
    float l_i[2] = {0.f, 0.f};
    float oacc[16][4];
    #pragma unroll
    for (int i = 0; i < 16; ++i)
        #pragma unroll
        for (int r = 0; r < 4; ++r) oacc[i][r] = 0.f;

    const int row_r = q0 + w * 16 + (lane >> 2);
    const int kt_lo = (q0 >= WIN) ? (q0 - WIN) : 0;

    for (int kt = kt_lo; kt <= q0; kt += 128) {
        __syncthreads();
        // ---- load K (RoPE fused) and V tiles, single fp16 ----
        #pragma unroll
        for (int i = 0; i < 16; ++i) {
            int v = tid + i * 256;
            int c = v >> 5, dq = (v & 31) * 4;
            int t = kt + c;
            const size_t tokbase = (size_t)(b * SEQ + t) * FDIM;
            float4 kk = *(const float4*)&g_qkv[tokbase + NHEAD * HD + kvh * HD + dq];
            int p0 = dq >> 1;
            float c0 = __ldg(&fcos[t * (HD/2) + p0]),     s0 = __ldg(&fsin[t * (HD/2) + p0]);
            float c1 = __ldg(&fcos[t * (HD/2) + p0 + 1]), s1 = __ldg(&fsin[t * (HD/2) + p0 + 1]);
            float r0 = kk.x * c0 - kk.y * s0, i0 = kk.x * s0 + kk.y * c0;
            float r1 = kk.z * c1 - kk.w * s1, i1 = kk.z * s1 + kk.w * c1;
            *(uint32_t*)&Kt[c * AROW + dq]     = pack_half2(r0, i0);
            *(uint32_t*)&Kt[c * AROW + dq + 2] = pack_half2(r1, i1);
            float4 vv = *(const float4*)&g_qkv[tokbase + (NHEAD + NKV) * HD + kvh * HD + dq];
            *(uint32_t*)&Vt[c * AROW + dq]     = pack_half2(vv.x, vv.y);
            *(uint32_t*)&Vt[c * AROW + dq + 2] = pack_half2(vv.z, vv.w);
        }
        __syncthreads();

        // ---- S = Q K^T (2-term fp16) ----
        float sacc[16][4];
        #pragma unroll
        for (int i = 0; i < 16; ++i)
            #pragma unroll
            for (int r = 0; r < 4; ++r) sacc[i][r] = 0.f;

        #pragma unroll
        for (int ks = 0; ks < 8; ++ks) {
            uint32_t aQh[4], aQl[4];
            uint32_t aoff = (uint32_t)((w * 16 + (lane & 7) + (lg & 1) * 8) * AROW_B
                                       + (ks * 16 + (lg >> 1) * 8) * 2);
            ldmatrix_x4(aQh, sQh + aoff);
            ldmatrix_x4(aQl, sQl + aoff);
            #pragma unroll
            for (int p16 = 0; p16 < 8; ++p16) {
                uint32_t bK[4];
                uint32_t boff = (uint32_t)((p16 * 16 + (lane & 7) + (lg >> 1) * 8) * AROW_B
                                           + (ks * 16 + (lg & 1) * 8) * 2);
                ldmatrix_x4(bK, sK + boff);
                mma_fp16(sacc[2*p16],   aQh, &bK[0]);
                mma_fp16(sacc[2*p16+1], aQh, &bK[2]);
                mma_fp16(sacc[2*p16],   aQl, &bK[0]);
                mma_fp16(sacc[2*p16+1], aQl, &bK[2]);
            }
        }

        // ---- mask + scale ----
        #pragma unroll
        for (int nf = 0; nf < 16; ++nf) {
            int col = kt + nf * 8 + (lane & 3) * 2;
            #pragma unroll
            for (int e = 0; e < 2; ++e) {
                int cj = col + e;
                bool k0 = (cj <= row_r)     && (cj >= row_r - (WIN - 1));
                bool k1 = (cj <= row_r + 8) && (cj >= row_r + 8 - (WIN - 1));
                sacc[nf][e]     = k0 ? sacc[nf][e]     * ATT_SCALE : -1e30f;
                sacc[nf][e + 2] = k1 ? sacc[nf][e + 2] * ATT_SCALE : -1e30f;
            }
        }

        // ---- online softmax ----
        float mx0 = -1e30f, mx1 = -1e30f;
        #pragma unroll
        for (int nf = 0; nf < 16; ++nf) {
            mx0 = fmaxf(mx0, fmaxf(sacc[nf][0], sacc[nf][1]));
            mx1 = fmaxf(mx1, fmaxf(sacc[nf][2], sacc[nf][3]));
        }
        #pragma unroll
        for (int o = 1; o < 4; o <<= 1) {
            mx0 = fmaxf(mx0, __shfl_xor_sync(0xffffffffu, mx0, o));
            mx1 = fmaxf(mx1, __shfl_xor_sync(0xffffffffu, mx1, o));
        }
        float mn0 = fmaxf(m_i[0], mx0), mn1 = fmaxf(m_i[1], mx1);
        float al0 = __expf(m_i[0] - mn0), al1 = __expf(m_i[1] - mn1);
        float rs0 = 0.f, rs1 = 0.f;
        #pragma unroll
        for (int nf = 0; nf < 16; ++nf) {
            sacc[nf][0] = __expf(sacc[nf][0] - mn0);
            sacc[nf][1] = __expf(sacc[nf][1] - mn0);
            sacc[nf][2] = __expf(sacc[nf][2] - mn1);
            sacc[nf][3] = __expf(sacc[nf][3] - mn1);
            rs0 += sacc[nf][0] + sacc[nf][1];
            rs1 += sacc[nf][2] + sacc[nf][3];
        }
        #pragma unroll
        for (int o = 1; o < 4; o <<= 1) {
            rs0 += __shfl_xor_sync(0xffffffffu, rs0, o);
            rs1 += __shfl_xor_sync(0xffffffffu, rs1, o);
        }
        l_i[0] = l_i[0] * al0 + rs0;  m_i[0] = mn0;
        l_i[1] = l_i[1] * al1 + rs1;  m_i[1] = mn1;
        #pragma unroll
        for (int nf = 0; nf < 16; ++nf) {
            oacc[nf][0] *= al0; oacc[nf][1] *= al0;
            oacc[nf][2] *= al1; oacc[nf][3] *= al1;
        }

        // ---- O += P V (2-term: P split fp16, V single) ----
        #pragma unroll
        for (int kc = 0; kc < 8; ++kc) {
            uint32_t aph[4], apl[4];
            #pragma unroll
            for (int half = 0; half < 2; ++half) {
                const float* sf = sacc[2 * kc + half];
                __half h0 = __float2half_rn(sf[0]);
                __half h1 = __float2half_rn(sf[1]);
                __half h2 = __float2half_rn(sf[2]);
                __half h3 = __float2half_rn(sf[3]);
                aph[half * 2 + 0] = pack_half2(__half2float(h0), __half2float(h1));
                aph[half * 2 + 1] = pack_half2(__half2float(h2), __half2float(h3));
                apl[half * 2 + 0] = pack_half2(sf[0] - __half2float(h0),
                                               sf[1] - __half2float(h1));
                apl[half * 2 + 1] = pack_half2(sf[2] - __half2float(h2),
                                               sf[3] - __half2float(h3));
            }
            #pragma unroll
            for (int p16 = 0; p16 < 8; ++p16) {
                uint32_t bV[4];
                uint32_t boff = (uint32_t)((kc * 16 + (lane & 7) + (lg & 1) * 8) * AROW_B
                                           + (p16 * 16 + (lg >> 1) * 8) * 2);
                ldmatrix_x4_trans(bV, sV + boff);
                mma_fp16(oacc[2*p16],   aph, &bV[0]);
                mma_fp16(oacc[2*p16+1], aph, &bV[2]);
                mma_fp16(oacc[2*p16],   apl, &bV[0]);
                mma_fp16(oacc[2*p16+1], apl, &bV[2]);
            }
        }
    }

    // ---- normalize, split hi/lo fp16, write y ----
    float inv0 = 1.f / l_i[0];
    float inv1 = 1.f / l_i[1];
    #pragma unroll
    for (int nf = 0; nf < 16; ++nf) {
        int d0 = nf * 8 + (lane & 3) * 2;
        size_t base0 = (size_t)(b * SEQ + row_r)     * CDIM + h * HD + d0;
        size_t base1 = (size_t)(b * SEQ + row_r + 8) * CDIM + h * HD + d0;
        float v00 = oacc[nf][0] * inv0, v01 = oacc[nf][1] * inv0;
        float v10 = oacc[nf][2] * inv1, v11 = oacc[nf][3] * inv1;
        __half h00 = __float2half_rn(v00), h01 = __float2half_rn(v01);
        __half h10 = __float2half_rn(v10), h11 = __float2half_rn(v11);
        *(uint32_t*)&g_yh[base0] = pack_half2(__half2float(h00), __half2float(h01));
        *(uint32_t*)&g_yl[base0] = pack_half2(v00 - __half2float(h00),
                                              v01 - __half2float(h01));
        *(uint32_t*)&g_yh[base1] = pack_half2(__half2float(h10), __half2float(h11));
        *(uint32_t*)&g_yl[base1] = pack_half2(v10 - __half2float(h10),
                                              v11 - __half2float(h11));
    }
}

// ---------------------------------------------------------------------------
extern "C" void kernel_launch(void* const* d_in, const int* in_sizes, int n_in,
                              void* d_out, int out_size)
{
    (void)in_sizes; (void)n_in; (void)out_size;
    const float* x      = (const float*)d_in[0];
    const float* w_qkv  = (const float*)d_in[1];
    const float* w_proj = (const float*)d_in[2];
    const float* fcos   = (const float*)d_in[3];
    const float* fsin   = (const float*)d_in[4];
    float* out = (float*)d_out;

    void *p_qkv, *p_xh, *p_xl, *p_wq, *p_wp, *p_yh, *p_yl;
    cudaGetSymbolAddress(&p_qkv, g_qkv);
    cudaGetSymbolAddress(&p_xh,  g_xh);
    cudaGetSymbolAddress(&p_xl,  g_xl);
    cudaGetSymbolAddress(&p_wq,  g_wq);
    cudaGetSymbolAddress(&p_wp,  g_wp);
    cudaGetSymbolAddress(&p_yh,  g_yh);
    cudaGetSymbolAddress(&p_yl,  g_yl);

    cudaFuncSetAttribute(gemm_fp16x2_kernel,
                         cudaFuncAttributeMaxDynamicSharedMemorySize, GEMM_SMEM);
    cudaFuncSetAttribute(attn_mma_kernel,
                         cudaFuncAttributeMaxDynamicSharedMemorySize, ATT_SMEM);

    // splits / converts
    {
        int n = MTOT * CDIM;
        split2_kernel<<<(n + 255) / 256, 256>>>(x, (__half*)p_xh, (__half*)p_xl, n);
        n = FDIM * CDIM;
        convert_kernel<<<(n + 255) / 256, 256>>>(w_qkv, (__half*)p_wq, n);
        n = CDIM * CDIM;
        convert_kernel<<<(n + 255) / 256, 256>>>(w_proj, (__half*)p_wp, n);
    }
    // QKV projection
    {
        dim3 grid(FDIM / 128, MTOT / 128);
        gemm_fp16x2_kernel<<<grid, 256, GEMM_SMEM>>>(
            (const __half*)p_xh, (const __half*)p_xl, (const __half*)p_wq,
            (float*)p_qkv, MTOT, FDIM, CDIM);
    }
    // Attention (RoPE fused into Q/K load)
    {
        dim3 grid(SEQ / 128, BATCH * NHEAD);
        attn_mma_kernel<<<grid, 256, ATT_SMEM>>>(fcos, fsin);
    }
    // Output projection
    {
        dim3 grid(CDIM / 128, MTOT / 128);
        gemm_fp16x2_kernel<<<grid, 256, GEMM_SMEM>>>(
            (const __half*)p_yh, (const __half*)p_yl, (const __half*)p_wp,
            out, MTOT, CDIM, CDIM);
    }
}

// round 14
// speedup vs baseline: 1.8964x; 1.1932x over previous
#include <cuda_runtime.h>
#include <cuda_fp16.h>
#include <cstdint>
#include <math.h>

#define BATCH 2
#define SEQ   2048
#define CDIM  2048
#define NHEAD 16
#define NKV   4
#define HD    128
#define NREP  4
#define WIN   512
#define FDIM  3072
#define MTOT  (BATCH*SEQ)   // 4096
#define ATT_SCALE 0.08838834764831845f

// ---------------- scratch (__device__ globals; no allocations) -------------
__device__ float  g_qkv[(size_t)MTOT * FDIM];
__device__ __half g_xh[(size_t)MTOT * CDIM];
__device__ __half g_wq[(size_t)FDIM * CDIM];
__device__ __half g_wp[(size_t)CDIM * CDIM];
__device__ __half g_yh[(size_t)MTOT * CDIM];
__device__ __half g_yl[(size_t)MTOT * CDIM];

// ---------------- helpers --------------------------------------------------
__device__ __forceinline__ uint32_t smem_to_u32(const void* p) {
    uint32_t a;
    asm("{ .reg .u64 t; cvta.to.shared.u64 t, %1; cvt.u32.u64 %0, t; }" : "=r"(a) : "l"(p));
    return a;
}
__device__ __forceinline__ void cp_async16(uint32_t dst, const void* src) {
    asm volatile("cp.async.cg.shared.global [%0], [%1], 16;" :: "r"(dst), "l"(src));
}
__device__ __forceinline__ void cp_commit() {
    asm volatile("cp.async.commit_group;");
}
template <int N>
__device__ __forceinline__ void cp_wait() {
    asm volatile("cp.async.wait_group %0;" :: "n"(N));
}
__device__ __forceinline__ void ldmatrix_x4(uint32_t* r, uint32_t addr) {
    asm volatile("ldmatrix.sync.aligned.m8n8.x4.shared.b16 {%0,%1,%2,%3}, [%4];"
        : "=r"(r[0]), "=r"(r[1]), "=r"(r[2]), "=r"(r[3]) : "r"(addr));
}
__device__ __forceinline__ void ldmatrix_x4_trans(uint32_t* r, uint32_t addr) {
    asm volatile("ldmatrix.sync.aligned.m8n8.x4.trans.shared.b16 {%0,%1,%2,%3}, [%4];"
        : "=r"(r[0]), "=r"(r[1]), "=r"(r[2]), "=r"(r[3]) : "r"(addr));
}
__device__ __forceinline__ void mma_fp16(float* c, const uint32_t* a, const uint32_t* b) {
    asm volatile(
        "mma.sync.aligned.m16n8k16.row.col.f32.f16.f16.f32 "
        "{%0,%1,%2,%3}, {%4,%5,%6,%7}, {%8,%9}, {%0,%1,%2,%3};"
        : "+f"(c[0]), "+f"(c[1]), "+f"(c[2]), "+f"(c[3])
        : "r"(a[0]), "r"(a[1]), "r"(a[2]), "r"(a[3]), "r"(b[0]), "r"(b[1]));
}
__device__ __forceinline__ uint32_t pack_half2(float lo, float hi) {
    __half2 t = __floats2half2_rn(lo, hi);
    return *(uint32_t*)&t;
}

// ---------------- converts -------------------------------------------------
__global__ void convert_kernel(const float* __restrict__ src,
                               __half* __restrict__ dst, int n)
{
    int i = blockIdx.x * blockDim.x + threadIdx.x;
    if (i >= n) return;
    dst[i] = __float2half_rn(src[i]);
}

// ---------------- fp16x1 NT GEMM: C = A * B^T (single-term) ----------------
// CTA 128x128, BK=32, 2-stage cp.async, one barrier per iter.
#define GPAD     40
#define GROW_B   (GPAD * 2)
#define GMAT_B   (128 * GROW_B)
#define G1STG_B  (2 * GMAT_B)          // A, B = 20480
#define GEMM1_SMEM (2 * G1STG_B)       // 40960

__global__ void __launch_bounds__(256)
gemm_fp16x1_kernel(const __half* __restrict__ A, const __half* __restrict__ B,
                   float* __restrict__ C, int M, int N, int K)
{
    extern __shared__ __align__(128) char smem[];
    const uint32_t sbase = smem_to_u32(smem);

    const int tid  = threadIdx.x;
    const int wid  = tid >> 5;
    const int lane = tid & 31;
    const int warp_m = wid & 1;
    const int warp_n = wid >> 1;
    const int m0 = blockIdx.y * 128;
    const int n0 = blockIdx.x * 128;

    float acc[4][4][4];
    #pragma unroll
    for (int i = 0; i < 4; ++i)
        #pragma unroll
        for (int j = 0; j < 4; ++j)
            #pragma unroll
            for (int r = 0; r < 4; ++r) acc[i][j][r] = 0.f;

    const int NIT = K >> 5;

    auto issue_stage = [&](int it) {
        const int s = it & 1;
        const int k0 = it * 32;
        const char* gA[2] = {
            (const char*)(A + (size_t)m0 * K + k0), (const char*)(B + (size_t)n0 * K + k0)};
        const size_t grs = (size_t)K * 2;
        #pragma unroll
        for (int t = 0; t < 2; ++t) {
            #pragma unroll
            for (int i = 0; i < 2; ++i) {
                int chunk = tid + i * 256;
                int r = chunk >> 2, c = (chunk & 3) * 16;
                uint32_t dst = sbase + s * G1STG_B + t * GMAT_B + r * GROW_B + c;
                cp_async16(dst, gA[t] + (size_t)r * grs + c);
            }
        }
        cp_commit();
    };

    issue_stage(0);

    for (int it = 0; it < NIT; ++it) {
        cp_wait<0>();
        __syncthreads();
        if (it + 1 < NIT) issue_stage(it + 1);

        const int s = it & 1;
        const uint32_t sA = sbase + s * G1STG_B + 0 * GMAT_B;
        const uint32_t sB = sbase + s * G1STG_B + 1 * GMAT_B;

        const int lg = lane >> 3;
        #pragma unroll
        for (int ks = 0; ks < 2; ++ks) {
            const int kc = ks * 16;
            uint32_t ah[4][4];
            #pragma unroll
            for (int mt = 0; mt < 4; ++mt) {
                uint32_t off = (uint32_t)((warp_m * 64 + mt * 16 + (lane & 7) + (lg & 1) * 8) * GROW_B
                                          + (kc + (lg >> 1) * 8) * 2);
                ldmatrix_x4(ah[mt], sA + off);
            }
            uint32_t bh[2][4];
            #pragma unroll
            for (int p = 0; p < 2; ++p) {
                uint32_t off = (uint32_t)((warp_n * 32 + p * 16 + (lane & 7) + (lg >> 1) * 8) * GROW_B
                                          + (kc + (lg & 1) * 8) * 2);
                ldmatrix_x4(bh[p], sB + off);
            }
            #pragma unroll
            for (int mt = 0; mt < 4; ++mt)
                #pragma unroll
                for (int nt = 0; nt < 4; ++nt)
                    mma_fp16(acc[mt][nt], ah[mt], &bh[nt >> 1][(nt & 1) * 2]);
        }
    }

    #pragma unroll
    for (int mt = 0; mt < 4; ++mt) {
        #pragma unroll
        for (int nt = 0; nt < 4; ++nt) {
            int m = m0 + warp_m * 64 + mt * 16 + (lane >> 2);
            int n = n0 + warp_n * 32 + nt * 8 + (lane & 3) * 2;
            *(float2*)&C[(size_t)m * N + n]       = make_float2(acc[mt][nt][0], acc[mt][nt][1]);
            *(float2*)&C[(size_t)(m + 8) * N + n] = make_float2(acc[mt][nt][2], acc[mt][nt][3]);
        }
    }
}

// ---------------- fp16x2 NT GEMM: C = (Ah+Al) * Bh^T (proj) ----------------
#define GSTG_B   (3 * GMAT_B)          // Ah, Al, Bh = 30720
#define GEMM_SMEM (2 * GSTG_B)         // 61440

__global__ void __launch_bounds__(256)
gemm_fp16x2_kernel(const __half* __restrict__ Ah, const __half* __restrict__ Al,
                   const __half* __restrict__ Bh,
                   float* __restrict__ C, int M, int N, int K)
{
    extern __shared__ __align__(128) char smem[];
    const uint32_t sbase = smem_to_u32(smem);

    const int tid  = threadIdx.x;
    const int wid  = tid >> 5;
    const int lane = tid & 31;
    const int warp_m = wid & 1;
    const int warp_n = wid >> 1;
    const int m0 = blockIdx.y * 128;
    const int n0 = blockIdx.x * 128;

    float acc[4][4][4];
    #pragma unroll
    for (int i = 0; i < 4; ++i)
        #pragma unroll
        for (int j = 0; j < 4; ++j)
            #pragma unroll
            for (int r = 0; r < 4; ++r) acc[i][j][r] = 0.f;

    const int NIT = K >> 5;

    auto issue_stage = [&](int it) {
        const int s = it & 1;
        const int k0 = it * 32;
        const char* gA[3] = {
            (const char*)(Ah + (size_t)m0 * K + k0), (const char*)(Al + (size_t)m0 * K + k0),
            (const char*)(Bh + (size_t)n0 * K + k0)};
        const size_t grs = (size_t)K * 2;
        #pragma unroll
        for (int t = 0; t < 3; ++t) {
            #pragma unroll
            for (int i = 0; i < 2; ++i) {
                int chunk = tid + i * 256;
                int r = chunk >> 2, c = (chunk & 3) * 16;
                uint32_t dst = sbase + s * GSTG_B + t * GMAT_B + r * GROW_B + c;
                cp_async16(dst, gA[t] + (size_t)r * grs + c);
            }
        }
        cp_commit();
    };

    issue_stage(0);

    for (int it = 0; it < NIT; ++it) {
        cp_wait<0>();
        __syncthreads();
        if (it + 1 < NIT) issue_stage(it + 1);

        const int s = it & 1;
        const uint32_t sA_h = sbase + s * GSTG_B + 0 * GMAT_B;
        const uint32_t sA_l = sbase + s * GSTG_B + 1 * GMAT_B;
        const uint32_t sB_h = sbase + s * GSTG_B + 2 * GMAT_B;

        const int lg = lane >> 3;
        #pragma unroll
        for (int ks = 0; ks < 2; ++ks) {
            const int kc = ks * 16;
            uint32_t ah[4][4], al[4][4];
            #pragma unroll
            for (int mt = 0; mt < 4; ++mt) {
                uint32_t off = (uint32_t)((warp_m * 64 + mt * 16 + (lane & 7) + (lg & 1) * 8) * GROW_B
                                          + (kc + (lg >> 1) * 8) * 2);
                ldmatrix_x4(ah[mt], sA_h + off);
                ldmatrix_x4(al[mt], sA_l + off);
            }
            uint32_t bh[2][4];
            #pragma unroll
            for (int p = 0; p < 2; ++p) {
                uint32_t off = (uint32_t)((warp_n * 32 + p * 16 + (lane & 7) + (lg >> 1) * 8) * GROW_B
                                          + (kc + (lg & 1) * 8) * 2);
                ldmatrix_x4(bh[p], sB_h + off);
            }
            #pragma unroll
            for (int mt = 0; mt < 4; ++mt)
                #pragma unroll
                for (int nt = 0; nt < 4; ++nt)
                    mma_fp16(acc[mt][nt], ah[mt], &bh[nt >> 1][(nt & 1) * 2]);
            #pragma unroll
            for (int mt = 0; mt < 4; ++mt)
                #pragma unroll
                for (int nt = 0; nt < 4; ++nt)
                    mma_fp16(acc[mt][nt], al[mt], &bh[nt >> 1][(nt & 1) * 2]);
        }
    }

    #pragma unroll
    for (int mt = 0; mt < 4; ++mt) {
        #pragma unroll
        for (int nt = 0; nt < 4; ++nt) {
            int m = m0 + warp_m * 64 + mt * 16 + (lane >> 2);
            int n = n0 + warp_n * 32 + nt * 8 + (lane & 3) * 2;
            *(float2*)&C[(size_t)m * N + n]       = make_float2(acc[mt][nt][0], acc[mt][nt][1]);
            *(float2*)&C[(size_t)(m + 8) * N + n] = make_float2(acc[mt][nt][2], acc[mt][nt][3]);
        }
    }
}

// ---------------- windowed flash attention, RoPE fused into Q/K load -------
#define AROW    136
#define AROW_B  (AROW * 2)
#define ABUF_B  (128 * AROW_B)
#define ATT_SMEM (4 * ABUF_B)          // Qh, Ql, K, V = 139264

__global__ void __launch_bounds__(256) attn_mma_kernel(
    const float* __restrict__ fcos, const float* __restrict__ fsin)
{
    extern __shared__ __align__(128) char asmem[];
    const uint32_t sb  = smem_to_u32(asmem);
    const uint32_t sQh = sb,              sQl = sb + ABUF_B;
    const uint32_t sK  = sb + 2*ABUF_B,   sV  = sb + 3*ABUF_B;
    __half* Qh = (__half*)asmem;
    __half* Ql = Qh + 128*AROW;
    __half* Kt = Qh + 2*128*AROW;
    __half* Vt = Qh + 3*128*AROW;

    const int tid  = threadIdx.x;
    const int w    = tid >> 5;
    const int lane = tid & 31;
    const int lg   = lane >> 3;
    const int bh   = blockIdx.y;
    const int b    = bh / NHEAD;
    const int h    = bh % NHEAD;
    const int kvh  = h / NREP;
    const int q0   = blockIdx.x * 128;

    // ---- load Q tile, apply RoPE (fp32), split hi/lo fp16 ----
    #pragma unroll
    for (int i = 0; i < 16; ++i) {
        int v = tid + i * 256;
        int m = v >> 5, dq = (v & 31) * 4;
        int t = q0 + m;
        float4 q = *(const float4*)&g_qkv[(size_t)(b * SEQ + t) * FDIM + h * HD + dq];
        int p0 = dq >> 1;
        float c0 = __ldg(&fcos[t * (HD/2) + p0]),     s0 = __ldg(&fsin[t * (HD/2) + p0]);
        float c1 = __ldg(&fcos[t * (HD/2) + p0 + 1]), s1 = __ldg(&fsin[t * (HD/2) + p0 + 1]);
        float f[4];
        f[0] = q.x * c0 - q.y * s0;  f[1] = q.x * s0 + q.y * c0;
        f[2] = q.z * c1 - q.w * s1;  f[3] = q.z * s1 + q.w * c1;
        #pragma unroll
        for (int e = 0; e < 4; e += 2) {
            __half h0 = __float2half_rn(f[e]);
            __half h1 = __float2half_rn(f[e+1]);
            *(uint32_t*)&Qh[m * AROW + dq + e] = pack_half2(__half2float(h0), __half2float(h1));
            *(uint32_t*)&Ql[m * AROW + dq + e] = pack_half2(f[e]   - __half2float(h0),
                                                            f[e+1] - __half2float(h1));
        }
    }

    float m_i[2] = {-1e30f, -1e30f};
    float l_i[2] = {0.f, 0.f};
    float oacc[16][4];
    #pragma unroll
    for (int i = 0; i < 16; ++i)
        #pragma unroll
        for (int r = 0; r < 4; ++r) oacc[i][r] = 0.f;

    const int row_r = q0 + w * 16 + (lane >> 2);
    const int kt_lo = (q0 >= WIN) ? (q0 - WIN) : 0;

    for (int kt = kt_lo; kt <= q0; kt += 128) {
        __syncthreads();
        // ---- load K (RoPE fused) and V tiles, single fp16 ----
        #pragma unroll
        for (int i = 0; i < 16; ++i) {
            int v = tid + i * 256;
            int c = v >> 5, dq = (v & 31) * 4;
            int t = kt + c;
            const size_t tokbase = (size_t)(b * SEQ + t) * FDIM;
            float4 kk = *(const float4*)&g_qkv[tokbase + NHEAD * HD + kvh * HD + dq];
            int p0 = dq >> 1;
            float c0 = __ldg(&fcos[t * (HD/2) + p0]),     s0 = __ldg(&fsin[t * (HD/2) + p0]);
            float c1 = __ldg(&fcos[t * (HD/2) + p0 + 1]), s1 = __ldg(&fsin[t * (HD/2) + p0 + 1]);
            float r0 = kk.x * c0 - kk.y * s0, i0 = kk.x * s0 + kk.y * c0;
            float r1 = kk.z * c1 - kk.w * s1, i1 = kk.z * s1 + kk.w * c1;
            *(uint32_t*)&Kt[c * AROW + dq]     = pack_half2(r0, i0);
            *(uint32_t*)&Kt[c * AROW + dq + 2] = pack_half2(r1, i1);
            float4 vv = *(const float4*)&g_qkv[tokbase + (NHEAD + NKV) * HD + kvh * HD + dq];
            *(uint32_t*)&Vt[c * AROW + dq]     = pack_half2(vv.x, vv.y);
            *(uint32_t*)&Vt[c * AROW + dq + 2] = pack_half2(vv.z, vv.w);
        }
        __syncthreads();

        // ---- S = Q K^T (2-term fp16) ----
        float sacc[16][4];
        #pragma unroll
        for (int i = 0; i < 16; ++i)
            #pragma unroll
            for (int r = 0; r < 4; ++r) sacc[i][r] = 0.f;

        #pragma unroll
        for (int ks = 0; ks < 8; ++ks) {
            uint32_t aQh[4], aQl[4];
            uint32_t aoff = (uint32_t)((w * 16 + (lane & 7) + (lg & 1) * 8) * AROW_B
                                       + (ks * 16 + (lg >> 1) * 8) * 2);
            ldmatrix_x4(aQh, sQh + aoff);
            ldmatrix_x4(aQl, sQl + aoff);
            #pragma unroll
            for (int p16 = 0; p16 < 8; ++p16) {
                uint32_t bK[4];
                uint32_t boff = (uint32_t)((p16 * 16 + (lane & 7) + (lg >> 1) * 8) * AROW_B
                                           + (ks * 16 + (lg & 1) * 8) * 2);
                ldmatrix_x4(bK, sK + boff);
                mma_fp16(sacc[2*p16],   aQh, &bK[0]);
                mma_fp16(sacc[2*p16+1], aQh, &bK[2]);
                mma_fp16(sacc[2*p16],   aQl, &bK[0]);
                mma_fp16(sacc[2*p16+1], aQl, &bK[2]);
            }
        }

        // ---- mask + scale ----
        #pragma unroll
        for (int nf = 0; nf < 16; ++nf) {
            int col = kt + nf * 8 + (lane & 3) * 2;
            #pragma unroll
            for (int e = 0; e < 2; ++e) {
                int cj = col + e;
                bool k0 = (cj <= row_r)     && (cj >= row_r - (WIN - 1));
                bool k1 = (cj <= row_r + 8) && (cj >= row_r + 8 - (WIN - 1));
                sacc[nf][e]     = k0 ? sacc[nf][e]     * ATT_SCALE : -1e30f;
                sacc[nf][e + 2] = k1 ? sacc[nf][e + 2] * ATT_SCALE : -1e30f;
            }
        }

        // ---- online softmax ----
        float mx0 = -1e30f, mx1 = -1e30f;
        #pragma unroll
        for (int nf = 0; nf < 16; ++nf) {
            mx0 = fmaxf(mx0, fmaxf(sacc[nf][0], sacc[nf][1]));
            mx1 = fmaxf(mx1, fmaxf(sacc[nf][2], sacc[nf][3]));
        }
        #pragma unroll
        for (int o = 1; o < 4; o <<= 1) {
            mx0 = fmaxf(mx0, __shfl_xor_sync(0xffffffffu, mx0, o));
            mx1 = fmaxf(mx1, __shfl_xor_sync(0xffffffffu, mx1, o));
        }
        float mn0 = fmaxf(m_i[0], mx0), mn1 = fmaxf(m_i[1], mx1);
        float al0 = __expf(m_i[0] - mn0), al1 = __expf(m_i[1] - mn1);
        float rs0 = 0.f, rs1 = 0.f;
        #pragma unroll
        for (int nf = 0; nf < 16; ++nf) {
            sacc[nf][0] = __expf(sacc[nf][0] - mn0);
            sacc[nf][1] = __expf(sacc[nf][1] - mn0);
            sacc[nf][2] = __expf(sacc[nf][2] - mn1);
            sacc[nf][3] = __expf(sacc[nf][3] - mn1);
            rs0 += sacc[nf][0] + sacc[nf][1];
            rs1 += sacc[nf][2] + sacc[nf][3];
        }
        #pragma unroll
        for (int o = 1; o < 4; o <<= 1) {
            rs0 += __shfl_xor_sync(0xffffffffu, rs0, o);
            rs1 += __shfl_xor_sync(0xffffffffu, rs1, o);
        }
        l_i[0] = l_i[0] * al0 + rs0;  m_i[0] = mn0;
        l_i[1] = l_i[1] * al1 + rs1;  m_i[1] = mn1;
        #pragma unroll
        for (int nf = 0; nf < 16; ++nf) {
            oacc[nf][0] *= al0; oacc[nf][1] *= al0;
            oacc[nf][2] *= al1; oacc[nf][3] *= al1;
        }

        // ---- O += P V (2-term: P split fp16, V single) ----
        #pragma unroll
        for (int kc = 0; kc < 8; ++kc) {
            uint32_t aph[4], apl[4];
            #pragma unroll
            for (int half = 0; half < 2; ++half) {
                const float* sf = sacc[2 * kc + half];
                __half h0 = __float2half_rn(sf[0]);
                __half h1 = __float2half_rn(sf[1]);
                __half h2 = __float2half_rn(sf[2]);
                __half h3 = __float2half_rn(sf[3]);
                aph[half * 2 + 0] = pack_half2(__half2float(h0), __half2float(h1));
                aph[half * 2 + 1] = pack_half2(__half2float(h2), __half2float(h3));
                apl[half * 2 + 0] = pack_half2(sf[0] - __half2float(h0),
                                               sf[1] - __half2float(h1));
                apl[half * 2 + 1] = pack_half2(sf[2] - __half2float(h2),
                                               sf[3] - __half2float(h3));
            }
            #pragma unroll
            for (int p16 = 0; p16 < 8; ++p16) {
                uint32_t bV[4];
                uint32_t boff = (uint32_t)((kc * 16 + (lane & 7) + (lg & 1) * 8) * AROW_B
                                           + (p16 * 16 + (lg >> 1) * 8) * 2);
                ldmatrix_x4_trans(bV, sV + boff);
                mma_fp16(oacc[2*p16],   aph, &bV[0]);
                mma_fp16(oacc[2*p16+1], aph, &bV[2]);
                mma_fp16(oacc[2*p16],   apl, &bV[0]);
                mma_fp16(oacc[2*p16+1], apl, &bV[2]);
            }
        }
    }

    // ---- normalize, split hi/lo fp16, write y ----
    float inv0 = 1.f / l_i[0];
    float inv1 = 1.f / l_i[1];
    #pragma unroll
    for (int nf = 0; nf < 16; ++nf) {
        int d0 = nf * 8 + (lane & 3) * 2;
        size_t base0 = (size_t)(b * SEQ + row_r)     * CDIM + h * HD + d0;
        size_t base1 = (size_t)(b * SEQ + row_r + 8) * CDIM + h * HD + d0;
        float v00 = oacc[nf][0] * inv0, v01 = oacc[nf][1] * inv0;
        float v10 = oacc[nf][2] * inv1, v11 = oacc[nf][3] * inv1;
        __half h00 = __float2half_rn(v00), h01 = __float2half_rn(v01);
        __half h10 = __float2half_rn(v10), h11 = __float2half_rn(v11);
        *(uint32_t*)&g_yh[base0] = pack_half2(__half2float(h00), __half2float(h01));
        *(uint32_t*)&g_yl[base0] = pack_half2(v00 - __half2float(h00),
                                              v01 - __half2float(h01));
        *(uint32_t*)&g_yh[base1] = pack_half2(__half2float(h10), __half2float(h11));
        *(uint32_t*)&g_yl[base1] = pack_half2(v10 - __half2float(h10),
                                              v11 - __half2float(h11));
    }
}

// ---------------------------------------------------------------------------
extern "C" void kernel_launch(void* const* d_in, const int* in_sizes, int n_in,
                              void* d_out, int out_size)
{
    (void)in_sizes; (void)n_in; (void)out_size;
    const float* x      = (const float*)d_in[0];
    const float* w_qkv  = (const float*)d_in[1];
    const float* w_proj = (const float*)d_in[2];
    const float* fcos   = (const float*)d_in[3];
    const float* fsin   = (const float*)d_in[4];
    float* out = (float*)d_out;

    void *p_qkv, *p_xh, *p_wq, *p_wp, *p_yh, *p_yl;
    cudaGetSymbolAddress(&p_qkv, g_qkv);
    cudaGetSymbolAddress(&p_xh,  g_xh);
    cudaGetSymbolAddress(&p_wq,  g_wq);
    cudaGetSymbolAddress(&p_wp,  g_wp);
    cudaGetSymbolAddress(&p_yh,  g_yh);
    cudaGetSymbolAddress(&p_yl,  g_yl);

    cudaFuncSetAttribute(gemm_fp16x1_kernel,
                         cudaFuncAttributeMaxDynamicSharedMemorySize, GEMM1_SMEM);
    cudaFuncSetAttribute(gemm_fp16x2_kernel,
                         cudaFuncAttributeMaxDynamicSharedMemorySize, GEMM_SMEM);
    cudaFuncSetAttribute(attn_mma_kernel,
                         cudaFuncAttributeMaxDynamicSharedMemorySize, ATT_SMEM);

    // converts
    {
        int n = MTOT * CDIM;
        convert_kernel<<<(n + 255) / 256, 256>>>(x, (__half*)p_xh, n);
        n = FDIM * CDIM;
        convert_kernel<<<(n + 255) / 256, 256>>>(w_qkv, (__half*)p_wq, n);
        n = CDIM * CDIM;
        convert_kernel<<<(n + 255) / 256, 256>>>(w_proj, (__half*)p_wp, n);
    }
    // QKV projection (fp16 single-term)
    {
        dim3 grid(FDIM / 128, MTOT / 128);
        gemm_fp16x1_kernel<<<grid, 256, GEMM1_SMEM>>>(
            (const __half*)p_xh, (const __half*)p_wq,
            (float*)p_qkv, MTOT, FDIM, CDIM);
    }
    // Attention (RoPE fused, 2-term)
    {
        dim3 grid(SEQ / 128, BATCH * NHEAD);
        attn_mma_kernel<<<grid, 256, ATT_SMEM>>>(fcos, fsin);
    }
    // Output projection (2-term)
    {
        dim3 grid(CDIM / 128, MTOT / 128);
        gemm_fp16x2_kernel<<<grid, 256, GEMM_SMEM>>>(
            (const __half*)p_yh, (const __half*)p_yl, (const __half*)p_wp,
            out, MTOT, CDIM, CDIM);
    }
}

// round 15
// speedup vs baseline: 2.2204x; 1.1709x over previous
#include <cuda_runtime.h>
#include <cuda_fp16.h>
#include <cstdint>
#include <math.h>

#define BATCH 2
#define SEQ   2048
#define CDIM  2048
#define NHEAD 16
#define NKV   4
#define HD    128
#define NREP  4
#define WIN   512
#define FDIM  3072
#define MTOT  (BATCH*SEQ)   // 4096
#define ATT_SCALE 0.08838834764831845f

// ---------------- scratch (__device__ globals; no allocations) -------------
__device__ float  g_qkv[(size_t)MTOT * FDIM];
__device__ __half g_xh[(size_t)MTOT * CDIM];
__device__ __half g_wq[(size_t)FDIM * CDIM];
__device__ __half g_wp[(size_t)CDIM * CDIM];
__device__ __half g_yh[(size_t)MTOT * CDIM];

// ---------------- helpers --------------------------------------------------
__device__ __forceinline__ uint32_t smem_to_u32(const void* p) {
    uint32_t a;
    asm("{ .reg .u64 t; cvta.to.shared.u64 t, %1; cvt.u32.u64 %0, t; }" : "=r"(a) : "l"(p));
    return a;
}
__device__ __forceinline__ void cp_async16(uint32_t dst, const void* src) {
    asm volatile("cp.async.cg.shared.global [%0], [%1], 16;" :: "r"(dst), "l"(src));
}
__device__ __forceinline__ void cp_commit() {
    asm volatile("cp.async.commit_group;");
}
template <int N>
__device__ __forceinline__ void cp_wait() {
    asm volatile("cp.async.wait_group %0;" :: "n"(N));
}
__device__ __forceinline__ void ldmatrix_x4(uint32_t* r, uint32_t addr) {
    asm volatile("ldmatrix.sync.aligned.m8n8.x4.shared.b16 {%0,%1,%2,%3}, [%4];"
        : "=r"(r[0]), "=r"(r[1]), "=r"(r[2]), "=r"(r[3]) : "r"(addr));
}
__device__ __forceinline__ void ldmatrix_x4_trans(uint32_t* r, uint32_t addr) {
    asm volatile("ldmatrix.sync.aligned.m8n8.x4.trans.shared.b16 {%0,%1,%2,%3}, [%4];"
        : "=r"(r[0]), "=r"(r[1]), "=r"(r[2]), "=r"(r[3]) : "r"(addr));
}
__device__ __forceinline__ void mma_fp16(float* c, const uint32_t* a, const uint32_t* b) {
    asm volatile(
        "mma.sync.aligned.m16n8k16.row.col.f32.f16.f16.f32 "
        "{%0,%1,%2,%3}, {%4,%5,%6,%7}, {%8,%9}, {%0,%1,%2,%3};"
        : "+f"(c[0]), "+f"(c[1]), "+f"(c[2]), "+f"(c[3])
        : "r"(a[0]), "r"(a[1]), "r"(a[2]), "r"(a[3]), "r"(b[0]), "r"(b[1]));
}
__device__ __forceinline__ uint32_t pack_half2(float lo, float hi) {
    __half2 t = __floats2half2_rn(lo, hi);
    return *(uint32_t*)&t;
}

// ---------------- converts -------------------------------------------------
__global__ void convert_kernel(const float* __restrict__ src,
                               __half* __restrict__ dst, int n)
{
    int i = blockIdx.x * blockDim.x + threadIdx.x;
    if (i >= n) return;
    dst[i] = __float2half_rn(src[i]);
}

// ---------------- fp16x1 NT GEMM: C = A * B^T ------------------------------
// CTA 128x128, BK=32, 2-stage cp.async, one barrier per iter.
#define GPAD     40
#define GROW_B   (GPAD * 2)
#define GMAT_B   (128 * GROW_B)
#define G1STG_B  (2 * GMAT_B)          // A, B = 20480
#define GEMM1_SMEM (2 * G1STG_B)       // 40960

__global__ void __launch_bounds__(256)
gemm_fp16x1_kernel(const __half* __restrict__ A, const __half* __restrict__ B,
                   float* __restrict__ C, int M, int N, int K)
{
    extern __shared__ __align__(128) char smem[];
    const uint32_t sbase = smem_to_u32(smem);

    const int tid  = threadIdx.x;
    const int wid  = tid >> 5;
    const int lane = tid & 31;
    const int warp_m = wid & 1;
    const int warp_n = wid >> 1;
    const int m0 = blockIdx.y * 128;
    const int n0 = blockIdx.x * 128;

    float acc[4][4][4];
    #pragma unroll
    for (int i = 0; i < 4; ++i)
        #pragma unroll
        for (int j = 0; j < 4; ++j)
            #pragma unroll
            for (int r = 0; r < 4; ++r) acc[i][j][r] = 0.f;

    const int NIT = K >> 5;

    auto issue_stage = [&](int it) {
        const int s = it & 1;
        const int k0 = it * 32;
        const char* gA[2] = {
            (const char*)(A + (size_t)m0 * K + k0), (const char*)(B + (size_t)n0 * K + k0)};
        const size_t grs = (size_t)K * 2;
        #pragma unroll
        for (int t = 0; t < 2; ++t) {
            #pragma unroll
            for (int i = 0; i < 2; ++i) {
                int chunk = tid + i * 256;
                int r = chunk >> 2, c = (chunk & 3) * 16;
                uint32_t dst = sbase + s * G1STG_B + t * GMAT_B + r * GROW_B + c;
                cp_async16(dst, gA[t] + (size_t)r * grs + c);
            }
        }
        cp_commit();
    };

    issue_stage(0);

    for (int it = 0; it < NIT; ++it) {
        cp_wait<0>();
        __syncthreads();
        if (it + 1 < NIT) issue_stage(it + 1);

        const int s = it & 1;
        const uint32_t sA = sbase + s * G1STG_B + 0 * GMAT_B;
        const uint32_t sB = sbase + s * G1STG_B + 1 * GMAT_B;

        const int lg = lane >> 3;
        #pragma unroll
        for (int ks = 0; ks < 2; ++ks) {
            const int kc = ks * 16;
            uint32_t ah[4][4];
            #pragma unroll
            for (int mt = 0; mt < 4; ++mt) {
                uint32_t off = (uint32_t)((warp_m * 64 + mt * 16 + (lane & 7) + (lg & 1) * 8) * GROW_B
                                          + (kc + (lg >> 1) * 8) * 2);
                ldmatrix_x4(ah[mt], sA + off);
            }
            uint32_t bh[2][4];
            #pragma unroll
            for (int p = 0; p < 2; ++p) {
                uint32_t off = (uint32_t)((warp_n * 32 + p * 16 + (lane & 7) + (lg >> 1) * 8) * GROW_B
                                          + (kc + (lg & 1) * 8) * 2);
                ldmatrix_x4(bh[p], sB + off);
            }
            #pragma unroll
            for (int mt = 0; mt < 4; ++mt)
                #pragma unroll
                for (int nt = 0; nt < 4; ++nt)
                    mma_fp16(acc[mt][nt], ah[mt], &bh[nt >> 1][(nt & 1) * 2]);
        }
    }

    #pragma unroll
    for (int mt = 0; mt < 4; ++mt) {
        #pragma unroll
        for (int nt = 0; nt < 4; ++nt) {
            int m = m0 + warp_m * 64 + mt * 16 + (lane >> 2);
            int n = n0 + warp_n * 32 + nt * 8 + (lane & 3) * 2;
            *(float2*)&C[(size_t)m * N + n]       = make_float2(acc[mt][nt][0], acc[mt][nt][1]);
            *(float2*)&C[(size_t)(m + 8) * N + n] = make_float2(acc[mt][nt][2], acc[mt][nt][3]);
        }
    }
}

// ---------------- windowed flash attention, RoPE fused into Q/K load -------
#define AROW    136
#define AROW_B  (AROW * 2)
#define ABUF_B  (128 * AROW_B)
#define ATT_SMEM (4 * ABUF_B)          // Qh, Ql, K, V = 139264

__global__ void __launch_bounds__(256) attn_mma_kernel(
    const float* __restrict__ fcos, const float* __restrict__ fsin)
{
    extern __shared__ __align__(128) char asmem[];
    const uint32_t sb  = smem_to_u32(asmem);
    const uint32_t sQh = sb,              sQl = sb + ABUF_B;
    const uint32_t sK  = sb + 2*ABUF_B,   sV  = sb + 3*ABUF_B;
    __half* Qh = (__half*)asmem;
    __half* Ql = Qh + 128*AROW;
    __half* Kt = Qh + 2*128*AROW;
    __half* Vt = Qh + 3*128*AROW;

    const int tid  = threadIdx.x;
    const int w    = tid >> 5;
    const int lane = tid & 31;
    const int lg   = lane >> 3;
    const int bh   = blockIdx.y;
    const int b    = bh / NHEAD;
    const int h    = bh % NHEAD;
    const int kvh  = h / NREP;
    const int q0   = blockIdx.x * 128;

    // ---- load Q tile, apply RoPE (fp32), split hi/lo fp16 ----
    #pragma unroll
    for (int i = 0; i < 16; ++i) {
        int v = tid + i * 256;
        int m = v >> 5, dq = (v & 31) * 4;
        int t = q0 + m;
        float4 q = *(const float4*)&g_qkv[(size_t)(b * SEQ + t) * FDIM + h * HD + dq];
        int p0 = dq >> 1;
        float c0 = __ldg(&fcos[t * (HD/2) + p0]),     s0 = __ldg(&fsin[t * (HD/2) + p0]);
        float c1 = __ldg(&fcos[t * (HD/2) + p0 + 1]), s1 = __ldg(&fsin[t * (HD/2) + p0 + 1]);
        float f[4];
        f[0] = q.x * c0 - q.y * s0;  f[1] = q.x * s0 + q.y * c0;
        f[2] = q.z * c1 - q.w * s1;  f[3] = q.z * s1 + q.w * c1;
        #pragma unroll
        for (int e = 0; e < 4; e += 2) {
            __half h0 = __float2half_rn(f[e]);
            __half h1 = __float2half_rn(f[e+1]);
            *(uint32_t*)&Qh[m * AROW + dq + e] = pack_half2(__half2float(h0), __half2float(h1));
            *(uint32_t*)&Ql[m * AROW + dq + e] = pack_half2(f[e]   - __half2float(h0),
                                                            f[e+1] - __half2float(h1));
        }
    }

    float m_i[2] = {-1e30f, -1e30f};
    float l_i[2] = {0.f, 0.f};
    float oacc[16][4];
    #pragma unroll
    for (int i = 0; i < 16; ++i)
        #pragma unroll
        for (int r = 0; r < 4; ++r) oacc[i][r] = 0.f;

    const int row_r = q0 + w * 16 + (lane >> 2);
    const int kt_lo = (q0 >= WIN) ? (q0 - WIN) : 0;

    for (int kt = kt_lo; kt <= q0; kt += 128) {
        __syncthreads();
        // ---- load K (RoPE fused) and V tiles, single fp16 ----
        #pragma unroll
        for (int i = 0; i < 16; ++i) {
            int v = tid + i * 256;
            int c = v >> 5, dq = (v & 31) * 4;
            int t = kt + c;
            const size_t tokbase = (size_t)(b * SEQ + t) * FDIM;
            float4 kk = *(const float4*)&g_qkv[tokbase + NHEAD * HD + kvh * HD + dq];
            int p0 = dq >> 1;
            float c0 = __ldg(&fcos[t * (HD/2) + p0]),     s0 = __ldg(&fsin[t * (HD/2) + p0]);
            float c1 = __ldg(&fcos[t * (HD/2) + p0 + 1]), s1 = __ldg(&fsin[t * (HD/2) + p0 + 1]);
            float r0 = kk.x * c0 - kk.y * s0, i0 = kk.x * s0 + kk.y * c0;
            float r1 = kk.z * c1 - kk.w * s1, i1 = kk.z * s1 + kk.w * c1;
            *(uint32_t*)&Kt[c * AROW + dq]     = pack_half2(r0, i0);
            *(uint32_t*)&Kt[c * AROW + dq + 2] = pack_half2(r1, i1);
            float4 vv = *(const float4*)&g_qkv[tokbase + (NHEAD + NKV) * HD + kvh * HD + dq];
            *(uint32_t*)&Vt[c * AROW + dq]     = pack_half2(vv.x, vv.y);
            *(uint32_t*)&Vt[c * AROW + dq + 2] = pack_half2(vv.z, vv.w);
        }
        __syncthreads();

        // ---- S = Q K^T (2-term fp16) ----
        float sacc[16][4];
        #pragma unroll
        for (int i = 0; i < 16; ++i)
            #pragma unroll
            for (int r = 0; r < 4; ++r) sacc[i][r] = 0.f;

        #pragma unroll
        for (int ks = 0; ks < 8; ++ks) {
            uint32_t aQh[4], aQl[4];
            uint32_t aoff = (uint32_t)((w * 16 + (lane & 7) + (lg & 1) * 8) * AROW_B
                                       + (ks * 16 + (lg >> 1) * 8) * 2);
            ldmatrix_x4(aQh, sQh + aoff);
            ldmatrix_x4(aQl, sQl + aoff);
            #pragma unroll
            for (int p16 = 0; p16 < 8; ++p16) {
                uint32_t bK[4];
                uint32_t boff = (uint32_t)((p16 * 16 + (lane & 7) + (lg >> 1) * 8) * AROW_B
                                           + (ks * 16 + (lg & 1) * 8) * 2);
                ldmatrix_x4(bK, sK + boff);
                mma_fp16(sacc[2*p16],   aQh, &bK[0]);
                mma_fp16(sacc[2*p16+1], aQh, &bK[2]);
                mma_fp16(sacc[2*p16],   aQl, &bK[0]);
                mma_fp16(sacc[2*p16+1], aQl, &bK[2]);
            }
        }

        // ---- mask + scale ----
        #pragma unroll
        for (int nf = 0; nf < 16; ++nf) {
            int col = kt + nf * 8 + (lane & 3) * 2;
            #pragma unroll
            for (int e = 0; e < 2; ++e) {
                int cj = col + e;
                bool k0 = (cj <= row_r)     && (cj >= row_r - (WIN - 1));
                bool k1 = (cj <= row_r + 8) && (cj >= row_r + 8 - (WIN - 1));
                sacc[nf][e]     = k0 ? sacc[nf][e]     * ATT_SCALE : -1e30f;
                sacc[nf][e + 2] = k1 ? sacc[nf][e + 2] * ATT_SCALE : -1e30f;
            }
        }

        // ---- online softmax ----
        float mx0 = -1e30f, mx1 = -1e30f;
        #pragma unroll
        for (int nf = 0; nf < 16; ++nf) {
            mx0 = fmaxf(mx0, fmaxf(sacc[nf][0], sacc[nf][1]));
            mx1 = fmaxf(mx1, fmaxf(sacc[nf][2], sacc[nf][3]));
        }
        #pragma unroll
        for (int o = 1; o < 4; o <<= 1) {
            mx0 = fmaxf(mx0, __shfl_xor_sync(0xffffffffu, mx0, o));
            mx1 = fmaxf(mx1, __shfl_xor_sync(0xffffffffu, mx1, o));
        }
        float mn0 = fmaxf(m_i[0], mx0), mn1 = fmaxf(m_i[1], mx1);
        float al0 = __expf(m_i[0] - mn0), al1 = __expf(m_i[1] - mn1);
        float rs0 = 0.f, rs1 = 0.f;
        #pragma unroll
        for (int nf = 0; nf < 16; ++nf) {
            sacc[nf][0] = __expf(sacc[nf][0] - mn0);
            sacc[nf][1] = __expf(sacc[nf][1] - mn0);
            sacc[nf][2] = __expf(sacc[nf][2] - mn1);
            sacc[nf][3] = __expf(sacc[nf][3] - mn1);
            rs0 += sacc[nf][0] + sacc[nf][1];
            rs1 += sacc[nf][2] + sacc[nf][3];
        }
        #pragma unroll
        for (int o = 1; o < 4; o <<= 1) {
            rs0 += __shfl_xor_sync(0xffffffffu, rs0, o);
            rs1 += __shfl_xor_sync(0xffffffffu, rs1, o);
        }
        l_i[0] = l_i[0] * al0 + rs0;  m_i[0] = mn0;
        l_i[1] = l_i[1] * al1 + rs1;  m_i[1] = mn1;
        #pragma unroll
        for (int nf = 0; nf < 16; ++nf) {
            oacc[nf][0] *= al0; oacc[nf][1] *= al0;
            oacc[nf][2] *= al1; oacc[nf][3] *= al1;
        }

        // ---- O += P V (2-term: P split fp16, V single) ----
        #pragma unroll
        for (int kc = 0; kc < 8; ++kc) {
            uint32_t aph[4], apl[4];
            #pragma unroll
            for (int half = 0; half < 2; ++half) {
                const float* sf = sacc[2 * kc + half];
                __half h0 = __float2half_rn(sf[0]);
                __half h1 = __float2half_rn(sf[1]);
                __half h2 = __float2half_rn(sf[2]);
                __half h3 = __float2half_rn(sf[3]);
                aph[half * 2 + 0] = pack_half2(__half2float(h0), __half2float(h1));
                aph[half * 2 + 1] = pack_half2(__half2float(h2), __half2float(h3));
                apl[half * 2 + 0] = pack_half2(sf[0] - __half2float(h0),
                                               sf[1] - __half2float(h1));
                apl[half * 2 + 1] = pack_half2(sf[2] - __half2float(h2),
                                               sf[3] - __half2float(h3));
            }
            #pragma unroll
            for (int p16 = 0; p16 < 8; ++p16) {
                uint32_t bV[4];
                uint32_t boff = (uint32_t)((kc * 16 + (lane & 7) + (lg & 1) * 8) * AROW_B
                                           + (p16 * 16 + (lg >> 1) * 8) * 2);
                ldmatrix_x4_trans(bV, sV + boff);
                mma_fp16(oacc[2*p16],   aph, &bV[0]);
                mma_fp16(oacc[2*p16+1], aph, &bV[2]);
                mma_fp16(oacc[2*p16],   apl, &bV[0]);
                mma_fp16(oacc[2*p16+1], apl, &bV[2]);
            }
        }
    }

    // ---- normalize, write y (single fp16) ----
    float inv0 = 1.f / l_i[0];
    float inv1 = 1.f / l_i[1];
    #pragma unroll
    for (int nf = 0; nf < 16; ++nf) {
        int d0 = nf * 8 + (lane & 3) * 2;
        size_t base0 = (size_t)(b * SEQ + row_r)     * CDIM + h * HD + d0;
        size_t base1 = (size_t)(b * SEQ + row_r + 8) * CDIM + h * HD + d0;
        *(uint32_t*)&g_yh[base0] = pack_half2(oacc[nf][0] * inv0, oacc[nf][1] * inv0);
        *(uint32_t*)&g_yh[base1] = pack_half2(oacc[nf][2] * inv1, oacc[nf][3] * inv1);
    }
}

// ---------------------------------------------------------------------------
extern "C" void kernel_launch(void* const* d_in, const int* in_sizes, int n_in,
                              void* d_out, int out_size)
{
    (void)in_sizes; (void)n_in; (void)out_size;
    const float* x      = (const float*)d_in[0];
    const float* w_qkv  = (const float*)d_in[1];
    const float* w_proj = (const float*)d_in[2];
    const float* fcos   = (const float*)d_in[3];
    const float* fsin   = (const float*)d_in[4];
    float* out = (float*)d_out;

    void *p_qkv, *p_xh, *p_wq, *p_wp, *p_yh;
    cudaGetSymbolAddress(&p_qkv, g_qkv);
    cudaGetSymbolAddress(&p_xh,  g_xh);
    cudaGetSymbolAddress(&p_wq,  g_wq);
    cudaGetSymbolAddress(&p_wp,  g_wp);
    cudaGetSymbolAddress(&p_yh,  g_yh);

    cudaFuncSetAttribute(gemm_fp16x1_kernel,
                         cudaFuncAttributeMaxDynamicSharedMemorySize, GEMM1_SMEM);
    cudaFuncSetAttribute(attn_mma_kernel,
                         cudaFuncAttributeMaxDynamicSharedMemorySize, ATT_SMEM);

    // converts
    {
        int n = MTOT * CDIM;
        convert_kernel<<<(n + 255) / 256, 256>>>(x, (__half*)p_xh, n);
        n = FDIM * CDIM;
        convert_kernel<<<(n + 255) / 256, 256>>>(w_qkv, (__half*)p_wq, n);
        n = CDIM * CDIM;
        convert_kernel<<<(n + 255) / 256, 256>>>(w_proj, (__half*)p_wp, n);
    }
    // QKV projection (fp16 single-term)
    {
        dim3 grid(FDIM / 128, MTOT / 128);
        gemm_fp16x1_kernel<<<grid, 256, GEMM1_SMEM>>>(
            (const __half*)p_xh, (const __half*)p_wq,
            (float*)p_qkv, MTOT, FDIM, CDIM);
    }
    // Attention (RoPE fused, 2-term)
    {
        dim3 grid(SEQ / 128, BATCH * NHEAD);
        attn_mma_kernel<<<grid, 256, ATT_SMEM>>>(fcos, fsin);
    }
    // Output projection (fp16 single-term)
    {
        dim3 grid(CDIM / 128, MTOT / 128);
        gemm_fp16x1_kernel<<<grid, 256, GEMM1_SMEM>>>(
            (const __half*)p_yh, (const __half*)p_wp,
            out, MTOT, CDIM, CDIM);
    }
}

// round 17
// speedup vs baseline: 2.3474x; 1.0572x over previous
#include <cuda_runtime.h>
#include <cuda_fp16.h>
#include <cstdint>
#include <math.h>

#define BATCH 2
#define SEQ   2048
#define CDIM  2048
#define NHEAD 16
#define NKV   4
#define HD    128
#define NREP  4
#define WIN   512
#define FDIM  3072
#define MTOT  (BATCH*SEQ)   // 4096
#define ATT_SCALE 0.08838834764831845f

// ---------------- scratch (__device__ globals; no allocations) -------------
__device__ __half g_qkvh[(size_t)MTOT * FDIM];   // fp16 qkv, RoPE already applied
__device__ __half g_xh[(size_t)MTOT * CDIM];
__device__ __half g_wq[(size_t)FDIM * CDIM];
__device__ __half g_wp[(size_t)CDIM * CDIM];
__device__ __half g_yh[(size_t)MTOT * CDIM];

// ---------------- helpers --------------------------------------------------
__device__ __forceinline__ uint32_t smem_to_u32(const void* p) {
    uint32_t a;
    asm("{ .reg .u64 t; cvta.to.shared.u64 t, %1; cvt.u32.u64 %0, t; }" : "=r"(a) : "l"(p));
    return a;
}
__device__ __forceinline__ void cp_async16(uint32_t dst, const void* src) {
    asm volatile("cp.async.cg.shared.global [%0], [%1], 16;" :: "r"(dst), "l"(src));
}
__device__ __forceinline__ void cp_commit() {
    asm volatile("cp.async.commit_group;");
}
template <int N>
__device__ __forceinline__ void cp_wait() {
    asm volatile("cp.async.wait_group %0;" :: "n"(N));
}
__device__ __forceinline__ void ldmatrix_x4(uint32_t* r, uint32_t addr) {
    asm volatile("ldmatrix.sync.aligned.m8n8.x4.shared.b16 {%0,%1,%2,%3}, [%4];"
        : "=r"(r[0]), "=r"(r[1]), "=r"(r[2]), "=r"(r[3]) : "r"(addr));
}
__device__ __forceinline__ void ldmatrix_x4_trans(uint32_t* r, uint32_t addr) {
    asm volatile("ldmatrix.sync.aligned.m8n8.x4.trans.shared.b16 {%0,%1,%2,%3}, [%4];"
        : "=r"(r[0]), "=r"(r[1]), "=r"(r[2]), "=r"(r[3]) : "r"(addr));
}
__device__ __forceinline__ void mma_fp16(float* c, const uint32_t* a, const uint32_t* b) {
    asm volatile(
        "mma.sync.aligned.m16n8k16.row.col.f32.f16.f16.f32 "
        "{%0,%1,%2,%3}, {%4,%5,%6,%7}, {%8,%9}, {%0,%1,%2,%3};"
        : "+f"(c[0]), "+f"(c[1]), "+f"(c[2]), "+f"(c[3])
        : "r"(a[0]), "r"(a[1]), "r"(a[2]), "r"(a[3]), "r"(b[0]), "r"(b[1]));
}
__device__ __forceinline__ uint32_t pack_half2(float lo, float hi) {
    __half2 t = __floats2half2_rn(lo, hi);
    return *(uint32_t*)&t;
}

// ---------------- converts -------------------------------------------------
__global__ void convert_kernel(const float* __restrict__ src,
                               __half* __restrict__ dst, int n)
{
    int i = blockIdx.x * blockDim.x + threadIdx.x;
    if (i >= n) return;
    dst[i] = __float2half_rn(src[i]);
}

// ---------------- fp16x1 NT GEMM mainloop macro pieces ---------------------
#define GPAD     40
#define GROW_B   (GPAD * 2)
#define GMAT_B   (128 * GROW_B)
#define G1STG_B  (2 * GMAT_B)          // A, B = 20480
#define GEMM1_SMEM (2 * G1STG_B)       // 40960

// ---- proj GEMM: fp32 output ----
__global__ void __launch_bounds__(256)
gemm_fp16x1_kernel(const __half* __restrict__ A, const __half* __restrict__ B,
                   float* __restrict__ C, int M, int N, int K)
{
    extern __shared__ __align__(128) char smem[];
    const uint32_t sbase = smem_to_u32(smem);

    const int tid  = threadIdx.x;
    const int wid  = tid >> 5;
    const int lane = tid & 31;
    const int warp_m = wid & 1;
    const int warp_n = wid >> 1;
    const int m0 = blockIdx.y * 128;
    const int n0 = blockIdx.x * 128;

    float acc[4][4][4];
    #pragma unroll
    for (int i = 0; i < 4; ++i)
        #pragma unroll
        for (int j = 0; j < 4; ++j)
            #pragma unroll
            for (int r = 0; r < 4; ++r) acc[i][j][r] = 0.f;

    const int NIT = K >> 5;

    auto issue_stage = [&](int it) {
        const int s = it & 1;
        const int k0 = it * 32;
        const char* gA[2] = {
            (const char*)(A + (size_t)m0 * K + k0), (const char*)(B + (size_t)n0 * K + k0)};
        const size_t grs = (size_t)K * 2;
        #pragma unroll
        for (int t = 0; t < 2; ++t) {
            #pragma unroll
            for (int i = 0; i < 2; ++i) {
                int chunk = tid + i * 256;
                int r = chunk >> 2, c = (chunk & 3) * 16;
                uint32_t dst = sbase + s * G1STG_B + t * GMAT_B + r * GROW_B + c;
                cp_async16(dst, gA[t] + (size_t)r * grs + c);
            }
        }
        cp_commit();
    };

    issue_stage(0);

    for (int it = 0; it < NIT; ++it) {
        cp_wait<0>();
        __syncthreads();
        if (it + 1 < NIT) issue_stage(it + 1);

        const int s = it & 1;
        const uint32_t sA = sbase + s * G1STG_B + 0 * GMAT_B;
        const uint32_t sB = sbase + s * G1STG_B + 1 * GMAT_B;

        const int lg = lane >> 3;
        #pragma unroll
        for (int ks = 0; ks < 2; ++ks) {
            const int kc = ks * 16;
            uint32_t ah[4][4];
            #pragma unroll
            for (int mt = 0; mt < 4; ++mt) {
                uint32_t off = (uint32_t)((warp_m * 64 + mt * 16 + (lane & 7) + (lg & 1) * 8) * GROW_B
                                          + (kc + (lg >> 1) * 8) * 2);
                ldmatrix_x4(ah[mt], sA + off);
            }
            uint32_t bh[2][4];
            #pragma unroll
            for (int p = 0; p < 2; ++p) {
                uint32_t off = (uint32_t)((warp_n * 32 + p * 16 + (lane & 7) + (lg >> 1) * 8) * GROW_B
                                          + (kc + (lg & 1) * 8) * 2);
                ldmatrix_x4(bh[p], sB + off);
            }
            #pragma unroll
            for (int mt = 0; mt < 4; ++mt)
                #pragma unroll
                for (int nt = 0; nt < 4; ++nt)
                    mma_fp16(acc[mt][nt], ah[mt], &bh[nt >> 1][(nt & 1) * 2]);
        }
    }

    #pragma unroll
    for (int mt = 0; mt < 4; ++mt) {
        #pragma unroll
        for (int nt = 0; nt < 4; ++nt) {
            int m = m0 + warp_m * 64 + mt * 16 + (lane >> 2);
            int n = n0 + warp_n * 32 + nt * 8 + (lane & 3) * 2;
            *(float2*)&C[(size_t)m * N + n]       = make_float2(acc[mt][nt][0], acc[mt][nt][1]);
            *(float2*)&C[(size_t)(m + 8) * N + n] = make_float2(acc[mt][nt][2], acc[mt][nt][3]);
        }
    }
}

// ---- QKV GEMM: RoPE in epilogue, fp16 output ----
__global__ void __launch_bounds__(256)
gemm_qkv_rope_kernel(const __half* __restrict__ A, const __half* __restrict__ B,
                     __half* __restrict__ C,
                     const float* __restrict__ fcos, const float* __restrict__ fsin,
                     int M, int N, int K)
{
    extern __shared__ __align__(128) char smem[];
    const uint32_t sbase = smem_to_u32(smem);

    const int tid  = threadIdx.x;
    const int wid  = tid >> 5;
    const int lane = tid & 31;
    const int warp_m = wid & 1;
    const int warp_n = wid >> 1;
    const int m0 = blockIdx.y * 128;
    const int n0 = blockIdx.x * 128;

    float acc[4][4][4];
    #pragma unroll
    for (int i = 0; i < 4; ++i)
        #pragma unroll
        for (int j = 0; j < 4; ++j)
            #pragma unroll
            for (int r = 0; r < 4; ++r) acc[i][j][r] = 0.f;

    const int NIT = K >> 5;

    auto issue_stage = [&](int it) {
        const int s = it & 1;
        const int k0 = it * 32;
        const char* gA[2] = {
            (const char*)(A + (size_t)m0 * K + k0), (const char*)(B + (size_t)n0 * K + k0)};
        const size_t grs = (size_t)K * 2;
        #pragma unroll
        for (int t = 0; t < 2; ++t) {
            #pragma unroll
            for (int i = 0; i < 2; ++i) {
                int chunk = tid + i * 256;
                int r = chunk >> 2, c = (chunk & 3) * 16;
                uint32_t dst = sbase + s * G1STG_B + t * GMAT_B + r * GROW_B + c;
                cp_async16(dst, gA[t] + (size_t)r * grs + c);
            }
        }
        cp_commit();
    };

    issue_stage(0);

    for (int it = 0; it < NIT; ++it) {
        cp_wait<0>();
        __syncthreads();
        if (it + 1 < NIT) issue_stage(it + 1);

        const int s = it & 1;
        const uint32_t sA = sbase + s * G1STG_B + 0 * GMAT_B;
        const uint32_t sB = sbase + s * G1STG_B + 1 * GMAT_B;

        const int lg = lane >> 3;
        #pragma unroll
        for (int ks = 0; ks < 2; ++ks) {
            const int kc = ks * 16;
            uint32_t ah[4][4];
            #pragma unroll
            for (int mt = 0; mt < 4; ++mt) {
                uint32_t off = (uint32_t)((warp_m * 64 + mt * 16 + (lane & 7) + (lg & 1) * 8) * GROW_B
                                          + (kc + (lg >> 1) * 8) * 2);
                ldmatrix_x4(ah[mt], sA + off);
            }
            uint32_t bh[2][4];
            #pragma unroll
            for (int p = 0; p < 2; ++p) {
                uint32_t off = (uint32_t)((warp_n * 32 + p * 16 + (lane & 7) + (lg >> 1) * 8) * GROW_B
                                          + (kc + (lg & 1) * 8) * 2);
                ldmatrix_x4(bh[p], sB + off);
            }
            #pragma unroll
            for (int mt = 0; mt < 4; ++mt)
                #pragma unroll
                for (int nt = 0; nt < 4; ++nt)
                    mma_fp16(acc[mt][nt], ah[mt], &bh[nt >> 1][(nt & 1) * 2]);
        }
    }

    // epilogue: RoPE on q/k columns (n < (NHEAD+NKV)*HD), write fp16
    #pragma unroll
    for (int mt = 0; mt < 4; ++mt) {
        #pragma unroll
        for (int nt = 0; nt < 4; ++nt) {
            int m = m0 + warp_m * 64 + mt * 16 + (lane >> 2);
            int n = n0 + warp_n * 32 + nt * 8 + (lane & 3) * 2;   // even
            float v0 = acc[mt][nt][0], v1 = acc[mt][nt][1];
            float w0 = acc[mt][nt][2], w1 = acc[mt][nt][3];
            if (n < (NHEAD + NKV) * HD) {
                int p = (n & (HD - 1)) >> 1;
                int t0 = m & (SEQ - 1);
                float c0 = __ldg(&fcos[t0 * (HD/2) + p]);
                float s0 = __ldg(&fsin[t0 * (HD/2) + p]);
                float c1 = __ldg(&fcos[(t0 + 8) * (HD/2) + p]);
                float s1 = __ldg(&fsin[(t0 + 8) * (HD/2) + p]);
                float r0 = v0 * c0 - v1 * s0, r1 = v0 * s0 + v1 * c0;
                v0 = r0; v1 = r1;
                float q0 = w0 * c1 - w1 * s1, q1 = w0 * s1 + w1 * c1;
                w0 = q0; w1 = q1;
            }
            *(uint32_t*)&C[(size_t)m * N + n]       = pack_half2(v0, v1);
            *(uint32_t*)&C[(size_t)(m + 8) * N + n] = pack_half2(w0, w1);
        }
    }
}

// ---------------- windowed flash attention (Q/K/V all fp16, rope done) -----
#define AROW    136
#define AROW_B  (AROW * 2)
#define ABUF_B  (128 * AROW_B)
#define ATT_SMEM (3 * ABUF_B)          // Q, K, V = 104448

__global__ void __launch_bounds__(256) attn_mma_kernel()
{
    extern __shared__ __align__(128) char asmem[];
    const uint32_t sb = smem_to_u32(asmem);
    const uint32_t sQ = sb, sK = sb + ABUF_B, sV = sb + 2*ABUF_B;

    const int tid  = threadIdx.x;
    const int w    = tid >> 5;
    const int lane = tid & 31;
    const int lg   = lane >> 3;
    const int bh   = blockIdx.y;
    const int b    = bh / NHEAD;
    const int h    = bh % NHEAD;
    const int kvh  = h / NREP;
    const int q0   = blockIdx.x * 128;

    // ---- load Q tile (fp16, rope applied): 128 rows x 128 halves ----
    #pragma unroll
    for (int i = 0; i < 8; ++i) {
        int chunk = tid + i * 256;                 // 0..2047
        int r = chunk >> 4, c8 = (chunk & 15) * 8; // 16 chunks/row, 8 halves each
        uint4 d = *(const uint4*)&g_qkvh[(size_t)(b * SEQ + q0 + r) * FDIM + h * HD + c8];
        *(uint4*)((char*)asmem + (size_t)r * AROW_B + c8 * 2) = d;
    }

    float m_i[2] = {-1e30f, -1e30f};
    float l_i[2] = {0.f, 0.f};
    float oacc[16][4];
    #pragma unroll
    for (int i = 0; i < 16; ++i)
        #pragma unroll
        for (int r = 0; r < 4; ++r) oacc[i][r] = 0.f;

    const int row_r = q0 + w * 16 + (lane >> 2);
    const int kt_lo = (q0 >= WIN) ? (q0 - WIN) : 0;

    for (int kt = kt_lo; kt <= q0; kt += 128) {
        __syncthreads();
        // ---- load K, V tiles (fp16) ----
        #pragma unroll
        for (int i = 0; i < 8; ++i) {
            int chunk = tid + i * 256;
            int r = chunk >> 4, c8 = (chunk & 15) * 8;
            const size_t tokbase = (size_t)(b * SEQ + kt + r) * FDIM;
            uint4 kk = *(const uint4*)&g_qkvh[tokbase + NHEAD * HD + kvh * HD + c8];
            *(uint4*)((char*)asmem + ABUF_B + (size_t)r * AROW_B + c8 * 2) = kk;
            uint4 vv = *(const uint4*)&g_qkvh[tokbase + (NHEAD + NKV) * HD + kvh * HD + c8];
            *(uint4*)((char*)asmem + 2*ABUF_B + (size_t)r * AROW_B + c8 * 2) = vv;
        }
        __syncthreads();

        // ---- S = Q K^T (1-term fp16) ----
        float sacc[16][4];
        #pragma unroll
        for (int i = 0; i < 16; ++i)
            #pragma unroll
            for (int r = 0; r < 4; ++r) sacc[i][r] = 0.f;

        #pragma unroll
        for (int ks = 0; ks < 8; ++ks) {
            uint32_t aQ[4];
            uint32_t aoff = (uint32_t)((w * 16 + (lane & 7) + (lg & 1) * 8) * AROW_B
                                       + (ks * 16 + (lg >> 1) * 8) * 2);
            ldmatrix_x4(aQ, sQ + aoff);
            #pragma unroll
            for (int p16 = 0; p16 < 8; ++p16) {
                uint32_t bK[4];
                uint32_t boff = (uint32_t)((p16 * 16 + (lane & 7) + (lg >> 1) * 8) * AROW_B
                                           + (ks * 16 + (lg & 1) * 8) * 2);
                ldmatrix_x4(bK, sK + boff);
                mma_fp16(sacc[2*p16],   aQ, &bK[0]);
                mma_fp16(sacc[2*p16+1], aQ, &bK[2]);
            }
        }

        // ---- mask + scale ----
        #pragma unroll
        for (int nf = 0; nf < 16; ++nf) {
            int col = kt + nf * 8 + (lane & 3) * 2;
            #pragma unroll
            for (int e = 0; e < 2; ++e) {
                int cj = col + e;
                bool k0 = (cj <= row_r)     && (cj >= row_r - (WIN - 1));
                bool k1 = (cj <= row_r + 8) && (cj >= row_r + 8 - (WIN - 1));
                sacc[nf][e]     = k0 ? sacc[nf][e]     * ATT_SCALE : -1e30f;
                sacc[nf][e + 2] = k1 ? sacc[nf][e + 2] * ATT_SCALE : -1e30f;
            }
        }

        // ---- online softmax ----
        float mx0 = -1e30f, mx1 = -1e30f;
        #pragma unroll
        for (int nf = 0; nf < 16; ++nf) {
            mx0 = fmaxf(mx0, fmaxf(sacc[nf][0], sacc[nf][1]));
            mx1 = fmaxf(mx1, fmaxf(sacc[nf][2], sacc[nf][3]));
        }
        #pragma unroll
        for (int o = 1; o < 4; o <<= 1) {
            mx0 = fmaxf(mx0, __shfl_xor_sync(0xffffffffu, mx0, o));
            mx1 = fmaxf(mx1, __shfl_xor_sync(0xffffffffu, mx1, o));
        }
        float mn0 = fmaxf(m_i[0], mx0), mn1 = fmaxf(m_i[1], mx1);
        float al0 = __expf(m_i[0] - mn0), al1 = __expf(m_i[1] - mn1);
        float rs0 = 0.f, rs1 = 0.f;
        #pragma unroll
        for (int nf = 0; nf < 16; ++nf) {
            sacc[nf][0] = __expf(sacc[nf][0] - mn0);
            sacc[nf][1] = __expf(sacc[nf][1] - mn0);
            sacc[nf][2] = __expf(sacc[nf][2] - mn1);
            sacc[nf][3] = __expf(sacc[nf][3] - mn1);
            rs0 += sacc[nf][0] + sacc[nf][1];
            rs1 += sacc[nf][2] + sacc[nf][3];
        }
        #pragma unroll
        for (int o = 1; o < 4; o <<= 1) {
            rs0 += __shfl_xor_sync(0xffffffffu, rs0, o);
            rs1 += __shfl_xor_sync(0xffffffffu, rs1, o);
        }
        l_i[0] = l_i[0] * al0 + rs0;  m_i[0] = mn0;
        l_i[1] = l_i[1] * al1 + rs1;  m_i[1] = mn1;
        #pragma unroll
        for (int nf = 0; nf < 16; ++nf) {
            oacc[nf][0] *= al0; oacc[nf][1] *= al0;
            oacc[nf][2] *= al1; oacc[nf][3] *= al1;
        }

        // ---- O += P V (2-term: P split fp16, V single) ----
        #pragma unroll
        for (int kc = 0; kc < 8; ++kc) {
            uint32_t aph[4], apl[4];
            #pragma unroll
            for (int half = 0; half < 2; ++half) {
                const float* sf = sacc[2 * kc + half];
                __half h0 = __float2half_rn(sf[0]);
                __half h1 = __float2half_rn(sf[1]);
                __half h2 = __float2half_rn(sf[2]);
                __half h3 = __float2half_rn(sf[3]);
                aph[half * 2 + 0] = pack_half2(__half2float(h0), __half2float(h1));
                aph[half * 2 + 1] = pack_half2(__half2float(h2), __half2float(h3));
                apl[half * 2 + 0] = pack_half2(sf[0] - __half2float(h0),
                                               sf[1] - __half2float(h1));
                apl[half * 2 + 1] = pack_half2(sf[2] - __half2float(h2),
                                               sf[3] - __half2float(h3));
            }
            #pragma unroll
            for (int p16 = 0; p16 < 8; ++p16) {
                uint32_t bV[4];
                uint32_t boff = (uint32_t)((kc * 16 + (lane & 7) + (lg & 1) * 8) * AROW_B
                                           + (p16 * 16 + (lg >> 1) * 8) * 2);
                ldmatrix_x4_trans(bV, sV + boff);
                mma_fp16(oacc[2*p16],   aph, &bV[0]);
                mma_fp16(oacc[2*p16+1], aph, &bV[2]);
                mma_fp16(oacc[2*p16],   apl, &bV[0]);
                mma_fp16(oacc[2*p16+1], apl, &bV[2]);
            }
        }
    }

    // ---- normalize, write y (single fp16) ----
    float inv0 = 1.f / l_i[0];
    float inv1 = 1.f / l_i[1];
    #pragma unroll
    for (int nf = 0; nf < 16; ++nf) {
        int d0 = nf * 8 + (lane & 3) * 2;
        size_t base0 = (size_t)(b * SEQ + row_r)     * CDIM + h * HD + d0;
        size_t base1 = (size_t)(b * SEQ + row_r + 8) * CDIM + h * HD + d0;
        *(uint32_t*)&g_yh[base0] = pack_half2(oacc[nf][0] * inv0, oacc[nf][1] * inv0);
        *(uint32_t*)&g_yh[base1] = pack_half2(oacc[nf][2] * inv1, oacc[nf][3] * inv1);
    }
}

// ---------------------------------------------------------------------------
extern "C" void kernel_launch(void* const* d_in, const int* in_sizes, int n_in,
                              void* d_out, int out_size)
{
    (void)in_sizes; (void)n_in; (void)out_size;
    const float* x      = (const float*)d_in[0];
    const float* w_qkv  = (const float*)d_in[1];
    const float* w_proj = (const float*)d_in[2];
    const float* fcos   = (const float*)d_in[3];
    const float* fsin   = (const float*)d_in[4];
    float* out = (float*)d_out;

    void *p_qkvh, *p_xh, *p_wq, *p_wp, *p_yh;
    cudaGetSymbolAddress(&p_qkvh, g_qkvh);
    cudaGetSymbolAddress(&p_xh,  g_xh);
    cudaGetSymbolAddress(&p_wq,  g_wq);
    cudaGetSymbolAddress(&p_wp,  g_wp);
    cudaGetSymbolAddress(&p_yh,  g_yh);

    cudaFuncSetAttribute(gemm_fp16x1_kernel,
                         cudaFuncAttributeMaxDynamicSharedMemorySize, GEMM1_SMEM);
    cudaFuncSetAttribute(gemm_qkv_rope_kernel,
                         cudaFuncAttributeMaxDynamicSharedMemorySize, GEMM1_SMEM);
    cudaFuncSetAttribute(attn_mma_kernel,
                         cudaFuncAttributeMaxDynamicSharedMemorySize, ATT_SMEM);

    // converts
    {
        int n = MTOT * CDIM;
        convert_kernel<<<(n + 255) / 256, 256>>>(x, (__half*)p_xh, n);
        n = FDIM * CDIM;
        convert_kernel<<<(n + 255) / 256, 256>>>(w_qkv, (__half*)p_wq, n);
        n = CDIM * CDIM;
        convert_kernel<<<(n + 255) / 256, 256>>>(w_proj, (__half*)p_wp, n);
    }
    // QKV projection (fp16, RoPE fused into epilogue)
    {
        dim3 grid(FDIM / 128, MTOT / 128);
        gemm_qkv_rope_kernel<<<grid, 256, GEMM1_SMEM>>>(
            (const __half*)p_xh, (const __half*)p_wq,
            (__half*)p_qkvh, fcos, fsin, MTOT, FDIM, CDIM);
    }
    // Attention (all-fp16 inputs, 1-term S, 2-term PV)
    {
        dim3 grid(SEQ / 128, BATCH * NHEAD);
        attn_mma_kernel<<<grid, 256, ATT_SMEM>>>();
    }
    // Output projection (fp16 single-term, fp32 out)
    {
        dim3 grid(CDIM / 128, MTOT / 128);
        gemm_fp16x1_kernel<<<grid, 256, GEMM1_SMEM>>>(
            (const __half*)p_yh, (const __half*)p_wp,
            out, MTOT, CDIM, CDIM);
    }
}